// round 7
// baseline (speedup 1.0000x reference)
#include <cuda_runtime.h>
#include <cstddef>
#include <cstdint>

#define BATCH 8
#define CIN 64
#define NPTS 4096
#define COUT 64
#define KNN 20
#define PARTS 4
#define PCAND (NPTS / PARTS)   // 1024 candidates per partition
#define TM 64                  // candidates per tile
#define NT (PCAND / TM)        // 16 tiles per partition
#define MG 8                   // candidate group (accumulator chains)

// scratch (device globals: no allocations allowed)
__device__ float g_y2p[(size_t)BATCH * NPTS * COUT];
__device__ float g_zp [(size_t)BATCH * NPTS * COUT];
__device__ float g_xx [(size_t)BATCH * NPTS];
__device__ float g_ptd[(size_t)BATCH * PARTS * KNN * NPTS];  // [b][p][k][n]
__device__ int   g_pti[(size_t)BATCH * PARTS * KNN * NPTS];

// ---------------------------------------------------------------------------
// cp.async helpers
// ---------------------------------------------------------------------------
__device__ __forceinline__ void cp16(void* s, const void* g) {
    unsigned sa = (unsigned)__cvta_generic_to_shared(s);
    asm volatile("cp.async.cg.shared.global [%0], [%1], 16;" :: "r"(sa), "l"(g));
}
__device__ __forceinline__ void cp_commit() {
    asm volatile("cp.async.commit_group;" ::: "memory");
}
__device__ __forceinline__ void cp_wait1() {
    asm volatile("cp.async.wait_group 1;" ::: "memory");
}
__device__ __forceinline__ void cp_wait0() {
    asm volatile("cp.async.wait_group 0;" ::: "memory");
}

// ---------------------------------------------------------------------------
// Kernel A: per-point projections + BN folding + ||x||^2
// ---------------------------------------------------------------------------
__global__ void __launch_bounds__(128) prep_kernel(
    const float* __restrict__ x, const float* __restrict__ W,
    const float* __restrict__ gamma, const float* __restrict__ beta,
    const float* __restrict__ rmean, const float* __restrict__ rvar)
{
    __shared__ float sW[COUT * 2 * CIN];
    __shared__ float sA[COUT], sC0[COUT];

    const int t = threadIdx.x;
    const int b = blockIdx.y;
    const int n = blockIdx.x * 128 + t;

    for (int i = t; i < 2048; i += 128)
        ((float4*)sW)[i] = ((const float4*)W)[i];
    if (t < COUT) {
        float a = rsqrtf(rvar[t] + 1e-5f) * gamma[t];
        sA[t] = a;
        sC0[t] = fmaf(-a, rmean[t], beta[t]);
    }
    __syncthreads();

    const float* xb = x + (size_t)b * CIN * NPTS;
    float xq[CIN];
#pragma unroll
    for (int c = 0; c < CIN; c++) xq[c] = xb[(size_t)c * NPTS + n];

    float xx = 0.f;
#pragma unroll
    for (int c = 0; c < CIN; c++) xx = fmaf(xq[c], xq[c], xx);
    g_xx[(size_t)b * NPTS + n] = xx;

    float* y2r = g_y2p + ((size_t)b * NPTS + n) * COUT;
    float* zr  = g_zp  + ((size_t)b * NPTS + n) * COUT;

#pragma unroll 1
    for (int o = 0; o < COUT; o++) {
        const float* wr = sW + o * 128;
        float s2 = 0.f, sz = 0.f;
#pragma unroll
        for (int c = 0; c < 16; c++) {
            float4 w1 = *(const float4*)(wr + c * 4);
            float4 w2 = *(const float4*)(wr + 64 + c * 4);
            float q0 = xq[4*c+0], q1 = xq[4*c+1], q2 = xq[4*c+2], q3 = xq[4*c+3];
            s2 = fmaf(q0, w2.x, s2); sz = fmaf(q0, w1.x - w2.x, sz);
            s2 = fmaf(q1, w2.y, s2); sz = fmaf(q1, w1.y - w2.y, sz);
            s2 = fmaf(q2, w2.z, s2); sz = fmaf(q2, w1.z - w2.z, sz);
            s2 = fmaf(q3, w2.w, s2); sz = fmaf(q3, w1.w - w2.w, sz);
        }
        float a = sA[o];
        y2r[o] = a * s2;
        zr[o]  = fmaf(a, sz, sC0[o]);
    }
}

// ---------------------------------------------------------------------------
// top-20 insertion (replace current max, rescan). Ascending-m scan with
// strict '<' reproduces lax.top_k lowest-index tiebreak.
// ---------------------------------------------------------------------------
__device__ __forceinline__ void insert20(float (&td)[KNN], int (&ti)[KNN],
                                         float& kmax, int& kpos,
                                         float d, int m)
{
#pragma unroll
    for (int k = 0; k < KNN; k++) {
        if (k == kpos) { td[k] = d; ti[k] = m; }
    }
    float mx = -1e30f; int mp = 0;
#pragma unroll
    for (int k = 0; k < KNN; k++) {
        if (td[k] > mx) { mx = td[k]; mp = k; }
    }
    kmax = mx; kpos = mp;
}

// ---------------------------------------------------------------------------
// Kernel B: partitioned distance + top-K. Block = 128 queries x 1 partition
// (1024 candidates). Tile staged [c][m] via cp.async double buffer; inner
// loop reads 4 candidates/channel via broadcast LDS.128, 8 acc chains.
// ---------------------------------------------------------------------------
__global__ void __launch_bounds__(128, 3) knn_part_kernel(
    const float* __restrict__ x)
{
    __shared__ float s_x[2][CIN][TM];   // [buf][c][m], 16KB each
    __shared__ float s_xx[2][TM];

    const int t = threadIdx.x;
    const int p = blockIdx.y;
    const int b = blockIdx.z;
    const int n = blockIdx.x * 128 + t;
    const int cbase = p * PCAND;

    const float* xb  = x    + (size_t)b * CIN * NPTS;
    const float* xxp = g_xx + (size_t)b * NPTS + cbase;

    // query row in registers
    float xq[CIN];
#pragma unroll
    for (int c = 0; c < CIN; c++) xq[c] = xb[(size_t)c * NPTS + n];

    float xxq;
    {
        float s0 = 0.f, s1 = 0.f, s2 = 0.f, s3 = 0.f;
#pragma unroll
        for (int c = 0; c < CIN; c += 4) {
            s0 = fmaf(xq[c+0], xq[c+0], s0);
            s1 = fmaf(xq[c+1], xq[c+1], s1);
            s2 = fmaf(xq[c+2], xq[c+2], s2);
            s3 = fmaf(xq[c+3], xq[c+3], s3);
        }
        xxq = (s0 + s1) + (s2 + s3);
    }

    float td[KNN]; int ti[KNN];
#pragma unroll
    for (int k = 0; k < KNN; k++) { td[k] = 1e30f; ti[k] = 0; }
    float kmax = 1e30f; int kpos = 0;

    // cp.async loader: thread -> (channel block, m quad)
    const int lc0 = t >> 4;        // 0..7
    const int lm4 = (t & 15) << 2; // 0,4,...,60

    // prologue: issue tile 0 into buf 0
    {
        const float* src = xb + cbase;
#pragma unroll
        for (int j = 0; j < 8; j++) {
            int c = j * 8 + lc0;
            cp16(&s_x[0][c][lm4], src + (size_t)c * NPTS + lm4);
        }
        if (t < 16) cp16(&s_xx[0][t * 4], xxp + t * 4);
        cp_commit();
    }

#pragma unroll 1
    for (int tile = 0; tile < NT; tile++) {
        const int buf = tile & 1;
        if (tile + 1 < NT) {
            const float* src = xb + cbase + (tile + 1) * TM;
#pragma unroll
            for (int j = 0; j < 8; j++) {
                int c = j * 8 + lc0;
                cp16(&s_x[buf ^ 1][c][lm4], src + (size_t)c * NPTS + lm4);
            }
            if (t < 16) cp16(&s_xx[buf ^ 1][t * 4], xxp + (tile + 1) * TM + t * 4);
            cp_commit();
            cp_wait1();
        } else {
            cp_wait0();
        }
        __syncthreads();

        const int mbase = cbase + tile * TM;
#pragma unroll 1
        for (int mg = 0; mg < TM; mg += MG) {
            float a0 = 0.f, a1 = 0.f, a2 = 0.f, a3 = 0.f;
            float a4 = 0.f, a5 = 0.f, a6 = 0.f, a7 = 0.f;
#pragma unroll 16
            for (int c = 0; c < CIN; c++) {
                const float4 u0 = *(const float4*)&s_x[buf][c][mg];
                const float4 u1 = *(const float4*)&s_x[buf][c][mg + 4];
                const float q = xq[c];
                a0 = fmaf(q, u0.x, a0); a1 = fmaf(q, u0.y, a1);
                a2 = fmaf(q, u0.z, a2); a3 = fmaf(q, u0.w, a3);
                a4 = fmaf(q, u1.x, a4); a5 = fmaf(q, u1.y, a5);
                a6 = fmaf(q, u1.z, a6); a7 = fmaf(q, u1.w, a7);
            }
            const float e0 = fmaf(a0, -2.f, xxq + s_xx[buf][mg + 0]);
            const float e1 = fmaf(a1, -2.f, xxq + s_xx[buf][mg + 1]);
            const float e2 = fmaf(a2, -2.f, xxq + s_xx[buf][mg + 2]);
            const float e3 = fmaf(a3, -2.f, xxq + s_xx[buf][mg + 3]);
            const float e4 = fmaf(a4, -2.f, xxq + s_xx[buf][mg + 4]);
            const float e5 = fmaf(a5, -2.f, xxq + s_xx[buf][mg + 5]);
            const float e6 = fmaf(a6, -2.f, xxq + s_xx[buf][mg + 6]);
            const float e7 = fmaf(a7, -2.f, xxq + s_xx[buf][mg + 7]);
            const float emin = fminf(fminf(fminf(e0, e1), fminf(e2, e3)),
                                     fminf(fminf(e4, e5), fminf(e6, e7)));
            if (emin < kmax) {
                if (e0 < kmax) insert20(td, ti, kmax, kpos, e0, mbase + mg + 0);
                if (e1 < kmax) insert20(td, ti, kmax, kpos, e1, mbase + mg + 1);
                if (e2 < kmax) insert20(td, ti, kmax, kpos, e2, mbase + mg + 2);
                if (e3 < kmax) insert20(td, ti, kmax, kpos, e3, mbase + mg + 3);
                if (e4 < kmax) insert20(td, ti, kmax, kpos, e4, mbase + mg + 4);
                if (e5 < kmax) insert20(td, ti, kmax, kpos, e5, mbase + mg + 5);
                if (e6 < kmax) insert20(td, ti, kmax, kpos, e6, mbase + mg + 6);
                if (e7 < kmax) insert20(td, ti, kmax, kpos, e7, mbase + mg + 7);
            }
        }
        __syncthreads();
    }

    // store partition-local top-20, coalesced over n
    float* tdo = g_ptd + (size_t)(b * PARTS + p) * KNN * NPTS + n;
    int*   tio = g_pti + (size_t)(b * PARTS + p) * KNN * NPTS + n;
#pragma unroll
    for (int k = 0; k < KNN; k++) {
        tdo[(size_t)k * NPTS] = td[k];
        tio[(size_t)k * NPTS] = ti[k];
    }
}

// ---------------------------------------------------------------------------
// Kernel C: merge 4 partition lists (ascending partition order preserves
// lowest-index tie-break) + fused gather-max + BN/leaky epilogue.
// ---------------------------------------------------------------------------
__global__ void __launch_bounds__(128) merge_kernel(float* __restrict__ out)
{
    const int t = threadIdx.x;
    const int b = blockIdx.y;
    const int n = blockIdx.x * 128 + t;

    const float* tdp = g_ptd + (size_t)b * PARTS * KNN * NPTS + n;
    const int*   tip = g_pti + (size_t)b * PARTS * KNN * NPTS + n;

    float td[KNN]; int ti[KNN];
#pragma unroll
    for (int k = 0; k < KNN; k++) {
        td[k] = tdp[(size_t)k * NPTS];
        ti[k] = tip[(size_t)k * NPTS];
    }
    float kmax = -1e30f; int kpos = 0;
#pragma unroll
    for (int k = 0; k < KNN; k++) {
        if (td[k] > kmax) { kmax = td[k]; kpos = k; }
    }

#pragma unroll 1
    for (int p = 1; p < PARTS; p++) {
        const float* tdq = tdp + (size_t)p * KNN * NPTS;
        const int*   tiq = tip + (size_t)p * KNN * NPTS;
#pragma unroll
        for (int k = 0; k < KNN; k++) {
            float d = tdq[(size_t)k * NPTS];
            if (d < kmax) {
                int m = tiq[(size_t)k * NPTS];
                insert20(td, ti, kmax, kpos, d, m);
            }
        }
    }

    // out[b][o][n] = leaky(zp[n][o] + max_k y2p[idx_k][o])
    const float* y2b = g_y2p + (size_t)b * NPTS * COUT;
    float4 acc[16];
#pragma unroll
    for (int j = 0; j < 16; j++) acc[j] = make_float4(-1e30f, -1e30f, -1e30f, -1e30f);

#pragma unroll
    for (int k = 0; k < KNN; k++) {
        const float4* row = (const float4*)(y2b + (size_t)ti[k] * COUT);
#pragma unroll
        for (int j = 0; j < 16; j++) {
            float4 v = row[j];
            acc[j].x = fmaxf(acc[j].x, v.x);
            acc[j].y = fmaxf(acc[j].y, v.y);
            acc[j].z = fmaxf(acc[j].z, v.z);
            acc[j].w = fmaxf(acc[j].w, v.w);
        }
    }

    const float4* zr = (const float4*)(g_zp + ((size_t)b * NPTS + n) * COUT);
    float* ob = out + (size_t)b * COUT * NPTS + n;
#pragma unroll
    for (int j = 0; j < 16; j++) {
        float4 z = zr[j];
        float r0 = z.x + acc[j].x; r0 = (r0 >= 0.f) ? r0 : 0.2f * r0;
        float r1 = z.y + acc[j].y; r1 = (r1 >= 0.f) ? r1 : 0.2f * r1;
        float r2 = z.z + acc[j].z; r2 = (r2 >= 0.f) ? r2 : 0.2f * r2;
        float r3 = z.w + acc[j].w; r3 = (r3 >= 0.f) ? r3 : 0.2f * r3;
        ob[(size_t)(4*j+0) * NPTS] = r0;
        ob[(size_t)(4*j+1) * NPTS] = r1;
        ob[(size_t)(4*j+2) * NPTS] = r2;
        ob[(size_t)(4*j+3) * NPTS] = r3;
    }
}

// ---------------------------------------------------------------------------
extern "C" void kernel_launch(void* const* d_in, const int* in_sizes, int n_in,
                              void* d_out, int out_size)
{
    const float* x     = (const float*)d_in[0];
    const float* W     = (const float*)d_in[1];
    const float* gamma = (const float*)d_in[2];
    const float* beta  = (const float*)d_in[3];
    const float* rmean = (const float*)d_in[4];
    const float* rvar  = (const float*)d_in[5];
    float* out = (float*)d_out;

    (void)in_sizes; (void)n_in; (void)out_size;

    prep_kernel<<<dim3(NPTS / 128, BATCH), 128>>>(x, W, gamma, beta, rmean, rvar);
    knn_part_kernel<<<dim3(NPTS / 128, PARTS, BATCH), 128>>>(x);
    merge_kernel<<<dim3(NPTS / 128, BATCH), 128>>>(out);
}

// round 8
// speedup vs baseline: 1.0286x; 1.0286x over previous
#include <cuda_runtime.h>
#include <cstddef>
#include <cstdint>

#define BATCH 8
#define CIN 64
#define NPTS 4096
#define COUT 64
#define KNN 20
#define PARTS 2
#define PCAND (NPTS / PARTS)   // 2048 candidates per partition
#define TM 64                  // candidates per tile
#define NT (PCAND / TM)        // 32 tiles per partition
#define MG 8                   // candidate group (accumulator chains)

// scratch (device globals: no allocations allowed)
__device__ float g_y2p[(size_t)BATCH * NPTS * COUT];
__device__ float g_zp [(size_t)BATCH * NPTS * COUT];
__device__ float g_xx [(size_t)BATCH * NPTS];
__device__ float g_ptd[(size_t)BATCH * PARTS * KNN * NPTS];  // [b][p][k][n]
__device__ int   g_pti[(size_t)BATCH * PARTS * KNN * NPTS];

// ---------------------------------------------------------------------------
// cp.async helpers
// ---------------------------------------------------------------------------
__device__ __forceinline__ void cp16(void* s, const void* g) {
    unsigned sa = (unsigned)__cvta_generic_to_shared(s);
    asm volatile("cp.async.cg.shared.global [%0], [%1], 16;" :: "r"(sa), "l"(g));
}
__device__ __forceinline__ void cp_commit() {
    asm volatile("cp.async.commit_group;" ::: "memory");
}
__device__ __forceinline__ void cp_wait1() {
    asm volatile("cp.async.wait_group 1;" ::: "memory");
}
__device__ __forceinline__ void cp_wait0() {
    asm volatile("cp.async.wait_group 0;" ::: "memory");
}

// ---------------------------------------------------------------------------
// Kernel A: per-point projections + BN folding + ||x||^2
// ---------------------------------------------------------------------------
__global__ void __launch_bounds__(128) prep_kernel(
    const float* __restrict__ x, const float* __restrict__ W,
    const float* __restrict__ gamma, const float* __restrict__ beta,
    const float* __restrict__ rmean, const float* __restrict__ rvar)
{
    __shared__ float sW[COUT * 2 * CIN];
    __shared__ float sA[COUT], sC0[COUT];

    const int t = threadIdx.x;
    const int b = blockIdx.y;
    const int n = blockIdx.x * 128 + t;

    for (int i = t; i < 2048; i += 128)
        ((float4*)sW)[i] = ((const float4*)W)[i];
    if (t < COUT) {
        float a = rsqrtf(rvar[t] + 1e-5f) * gamma[t];
        sA[t] = a;
        sC0[t] = fmaf(-a, rmean[t], beta[t]);
    }
    __syncthreads();

    const float* xb = x + (size_t)b * CIN * NPTS;
    float xq[CIN];
#pragma unroll
    for (int c = 0; c < CIN; c++) xq[c] = xb[(size_t)c * NPTS + n];

    float xx = 0.f;
#pragma unroll
    for (int c = 0; c < CIN; c++) xx = fmaf(xq[c], xq[c], xx);
    g_xx[(size_t)b * NPTS + n] = xx;

    float* y2r = g_y2p + ((size_t)b * NPTS + n) * COUT;
    float* zr  = g_zp  + ((size_t)b * NPTS + n) * COUT;

#pragma unroll 1
    for (int o = 0; o < COUT; o++) {
        const float* wr = sW + o * 128;
        float s2 = 0.f, sz = 0.f;
#pragma unroll
        for (int c = 0; c < 16; c++) {
            float4 w1 = *(const float4*)(wr + c * 4);
            float4 w2 = *(const float4*)(wr + 64 + c * 4);
            float q0 = xq[4*c+0], q1 = xq[4*c+1], q2 = xq[4*c+2], q3 = xq[4*c+3];
            s2 = fmaf(q0, w2.x, s2); sz = fmaf(q0, w1.x - w2.x, sz);
            s2 = fmaf(q1, w2.y, s2); sz = fmaf(q1, w1.y - w2.y, sz);
            s2 = fmaf(q2, w2.z, s2); sz = fmaf(q2, w1.z - w2.z, sz);
            s2 = fmaf(q3, w2.w, s2); sz = fmaf(q3, w1.w - w2.w, sz);
        }
        float a = sA[o];
        y2r[o] = a * s2;
        zr[o]  = fmaf(a, sz, sC0[o]);
    }
}

// ---------------------------------------------------------------------------
// top-20 insertion (replace current max, rescan). Ascending-m scan with
// strict '<' reproduces lax.top_k lowest-index tiebreak.
// ---------------------------------------------------------------------------
__device__ __forceinline__ void insert20(float (&td)[KNN], int (&ti)[KNN],
                                         float& kmax, int& kpos,
                                         float d, int m)
{
#pragma unroll
    for (int k = 0; k < KNN; k++) {
        if (k == kpos) { td[k] = d; ti[k] = m; }
    }
    float mx = -1e30f; int mp = 0;
#pragma unroll
    for (int k = 0; k < KNN; k++) {
        if (td[k] > mx) { mx = td[k]; mp = k; }
    }
    kmax = mx; kpos = mp;
}

// ---------------------------------------------------------------------------
// Kernel B: partitioned distance + top-K. Block = 128 queries x 1 partition
// (2048 candidates). Tile staged [c][m] via cp.async double buffer; inner
// loop reads 4 candidates/channel via broadcast LDS.128, 8 acc chains.
// NOTE: min-blocks deliberately 2 (reg cap 256) — a cap of 3 forces spills
// of td/ti/xq to local memory (R7 post-mortem: 2.7x regression).
// ---------------------------------------------------------------------------
__global__ void __launch_bounds__(128, 2) knn_part_kernel(
    const float* __restrict__ x)
{
    __shared__ float s_x[2][CIN][TM];   // [buf][c][m], 16KB each
    __shared__ float s_xx[2][TM];

    const int t = threadIdx.x;
    const int p = blockIdx.y;
    const int b = blockIdx.z;
    const int n = blockIdx.x * 128 + t;
    const int cbase = p * PCAND;

    const float* xb  = x    + (size_t)b * CIN * NPTS;
    const float* xxp = g_xx + (size_t)b * NPTS + cbase;

    // query row in registers
    float xq[CIN];
#pragma unroll
    for (int c = 0; c < CIN; c++) xq[c] = xb[(size_t)c * NPTS + n];

    float xxq;
    {
        float s0 = 0.f, s1 = 0.f, s2 = 0.f, s3 = 0.f;
#pragma unroll
        for (int c = 0; c < CIN; c += 4) {
            s0 = fmaf(xq[c+0], xq[c+0], s0);
            s1 = fmaf(xq[c+1], xq[c+1], s1);
            s2 = fmaf(xq[c+2], xq[c+2], s2);
            s3 = fmaf(xq[c+3], xq[c+3], s3);
        }
        xxq = (s0 + s1) + (s2 + s3);
    }

    float td[KNN]; int ti[KNN];
#pragma unroll
    for (int k = 0; k < KNN; k++) { td[k] = 1e30f; ti[k] = 0; }
    float kmax = 1e30f; int kpos = 0;

    // cp.async loader: thread -> (channel block, m quad)
    const int lc0 = t >> 4;        // 0..7
    const int lm4 = (t & 15) << 2; // 0,4,...,60

    // prologue: issue tile 0 into buf 0
    {
        const float* src = xb + cbase;
#pragma unroll
        for (int j = 0; j < 8; j++) {
            int c = j * 8 + lc0;
            cp16(&s_x[0][c][lm4], src + (size_t)c * NPTS + lm4);
        }
        if (t < 16) cp16(&s_xx[0][t * 4], xxp + t * 4);
        cp_commit();
    }

#pragma unroll 1
    for (int tile = 0; tile < NT; tile++) {
        const int buf = tile & 1;
        if (tile + 1 < NT) {
            const float* src = xb + cbase + (tile + 1) * TM;
#pragma unroll
            for (int j = 0; j < 8; j++) {
                int c = j * 8 + lc0;
                cp16(&s_x[buf ^ 1][c][lm4], src + (size_t)c * NPTS + lm4);
            }
            if (t < 16) cp16(&s_xx[buf ^ 1][t * 4], xxp + (tile + 1) * TM + t * 4);
            cp_commit();
            cp_wait1();
        } else {
            cp_wait0();
        }
        __syncthreads();

        const int mbase = cbase + tile * TM;
#pragma unroll 1
        for (int mg = 0; mg < TM; mg += MG) {
            float a0 = 0.f, a1 = 0.f, a2 = 0.f, a3 = 0.f;
            float a4 = 0.f, a5 = 0.f, a6 = 0.f, a7 = 0.f;
#pragma unroll 16
            for (int c = 0; c < CIN; c++) {
                const float4 u0 = *(const float4*)&s_x[buf][c][mg];
                const float4 u1 = *(const float4*)&s_x[buf][c][mg + 4];
                const float q = xq[c];
                a0 = fmaf(q, u0.x, a0); a1 = fmaf(q, u0.y, a1);
                a2 = fmaf(q, u0.z, a2); a3 = fmaf(q, u0.w, a3);
                a4 = fmaf(q, u1.x, a4); a5 = fmaf(q, u1.y, a5);
                a6 = fmaf(q, u1.z, a6); a7 = fmaf(q, u1.w, a7);
            }
            const float e0 = fmaf(a0, -2.f, xxq + s_xx[buf][mg + 0]);
            const float e1 = fmaf(a1, -2.f, xxq + s_xx[buf][mg + 1]);
            const float e2 = fmaf(a2, -2.f, xxq + s_xx[buf][mg + 2]);
            const float e3 = fmaf(a3, -2.f, xxq + s_xx[buf][mg + 3]);
            const float e4 = fmaf(a4, -2.f, xxq + s_xx[buf][mg + 4]);
            const float e5 = fmaf(a5, -2.f, xxq + s_xx[buf][mg + 5]);
            const float e6 = fmaf(a6, -2.f, xxq + s_xx[buf][mg + 6]);
            const float e7 = fmaf(a7, -2.f, xxq + s_xx[buf][mg + 7]);
            const float emin = fminf(fminf(fminf(e0, e1), fminf(e2, e3)),
                                     fminf(fminf(e4, e5), fminf(e6, e7)));
            if (emin < kmax) {
                if (e0 < kmax) insert20(td, ti, kmax, kpos, e0, mbase + mg + 0);
                if (e1 < kmax) insert20(td, ti, kmax, kpos, e1, mbase + mg + 1);
                if (e2 < kmax) insert20(td, ti, kmax, kpos, e2, mbase + mg + 2);
                if (e3 < kmax) insert20(td, ti, kmax, kpos, e3, mbase + mg + 3);
                if (e4 < kmax) insert20(td, ti, kmax, kpos, e4, mbase + mg + 4);
                if (e5 < kmax) insert20(td, ti, kmax, kpos, e5, mbase + mg + 5);
                if (e6 < kmax) insert20(td, ti, kmax, kpos, e6, mbase + mg + 6);
                if (e7 < kmax) insert20(td, ti, kmax, kpos, e7, mbase + mg + 7);
            }
        }
        __syncthreads();
    }

    // store partition-local top-20, coalesced over n
    float* tdo = g_ptd + (size_t)(b * PARTS + p) * KNN * NPTS + n;
    int*   tio = g_pti + (size_t)(b * PARTS + p) * KNN * NPTS + n;
#pragma unroll
    for (int k = 0; k < KNN; k++) {
        tdo[(size_t)k * NPTS] = td[k];
        tio[(size_t)k * NPTS] = ti[k];
    }
}

// ---------------------------------------------------------------------------
// Kernel C: merge partition lists (ascending partition order preserves
// lowest-index tie-break) + fused gather-max + BN/leaky epilogue.
// ---------------------------------------------------------------------------
__global__ void __launch_bounds__(128) merge_kernel(float* __restrict__ out)
{
    const int t = threadIdx.x;
    const int b = blockIdx.y;
    const int n = blockIdx.x * 128 + t;

    const float* tdp = g_ptd + (size_t)b * PARTS * KNN * NPTS + n;
    const int*   tip = g_pti + (size_t)b * PARTS * KNN * NPTS + n;

    float td[KNN]; int ti[KNN];
#pragma unroll
    for (int k = 0; k < KNN; k++) {
        td[k] = tdp[(size_t)k * NPTS];
        ti[k] = tip[(size_t)k * NPTS];
    }
    float kmax = -1e30f; int kpos = 0;
#pragma unroll
    for (int k = 0; k < KNN; k++) {
        if (td[k] > kmax) { kmax = td[k]; kpos = k; }
    }

#pragma unroll 1
    for (int p = 1; p < PARTS; p++) {
        const float* tdq = tdp + (size_t)p * KNN * NPTS;
        const int*   tiq = tip + (size_t)p * KNN * NPTS;
#pragma unroll
        for (int k = 0; k < KNN; k++) {
            float d = tdq[(size_t)k * NPTS];
            if (d < kmax) {
                int m = tiq[(size_t)k * NPTS];
                insert20(td, ti, kmax, kpos, d, m);
            }
        }
    }

    // out[b][o][n] = leaky(zp[n][o] + max_k y2p[idx_k][o])
    const float* y2b = g_y2p + (size_t)b * NPTS * COUT;
    float4 acc[16];
#pragma unroll
    for (int j = 0; j < 16; j++) acc[j] = make_float4(-1e30f, -1e30f, -1e30f, -1e30f);

#pragma unroll
    for (int k = 0; k < KNN; k++) {
        const float4* row = (const float4*)(y2b + (size_t)ti[k] * COUT);
#pragma unroll
        for (int j = 0; j < 16; j++) {
            float4 v = row[j];
            acc[j].x = fmaxf(acc[j].x, v.x);
            acc[j].y = fmaxf(acc[j].y, v.y);
            acc[j].z = fmaxf(acc[j].z, v.z);
            acc[j].w = fmaxf(acc[j].w, v.w);
        }
    }

    const float4* zr = (const float4*)(g_zp + ((size_t)b * NPTS + n) * COUT);
    float* ob = out + (size_t)b * COUT * NPTS + n;
#pragma unroll
    for (int j = 0; j < 16; j++) {
        float4 z = zr[j];
        float r0 = z.x + acc[j].x; r0 = (r0 >= 0.f) ? r0 : 0.2f * r0;
        float r1 = z.y + acc[j].y; r1 = (r1 >= 0.f) ? r1 : 0.2f * r1;
        float r2 = z.z + acc[j].z; r2 = (r2 >= 0.f) ? r2 : 0.2f * r2;
        float r3 = z.w + acc[j].w; r3 = (r3 >= 0.f) ? r3 : 0.2f * r3;
        ob[(size_t)(4*j+0) * NPTS] = r0;
        ob[(size_t)(4*j+1) * NPTS] = r1;
        ob[(size_t)(4*j+2) * NPTS] = r2;
        ob[(size_t)(4*j+3) * NPTS] = r3;
    }
}

// ---------------------------------------------------------------------------
extern "C" void kernel_launch(void* const* d_in, const int* in_sizes, int n_in,
                              void* d_out, int out_size)
{
    const float* x     = (const float*)d_in[0];
    const float* W     = (const float*)d_in[1];
    const float* gamma = (const float*)d_in[2];
    const float* beta  = (const float*)d_in[3];
    const float* rmean = (const float*)d_in[4];
    const float* rvar  = (const float*)d_in[5];
    float* out = (float*)d_out;

    (void)in_sizes; (void)n_in; (void)out_size;

    prep_kernel<<<dim3(NPTS / 128, BATCH), 128>>>(x, W, gamma, beta, rmean, rvar);
    knn_part_kernel<<<dim3(NPTS / 128, PARTS, BATCH), 128>>>(x);
    merge_kernel<<<dim3(NPTS / 128, BATCH), 128>>>(out);
}

// round 9
// speedup vs baseline: 1.9139x; 1.8606x over previous
#include <cuda_runtime.h>
#include <cstddef>
#include <cstdint>

#define BATCH 8
#define CIN 64
#define NPTS 4096
#define COUT 64
#define KNN 20
#define TN 128
#define TM 64
#define PARTS 2
#define PCAND (NPTS / PARTS)   // 2048 candidates per partition
#define NT (PCAND / TM)        // 32 tiles per partition

// scratch (device globals: no allocations allowed)
__device__ float g_y2p[(size_t)BATCH * NPTS * COUT];  // a*(x . W2)
__device__ float g_zp [(size_t)BATCH * NPTS * COUT];  // a*(x . (W1-W2)) + beta - a*mean
__device__ float g_xx [(size_t)BATCH * NPTS];         // ||x_n||^2
__device__ float g_ptd[(size_t)BATCH * PARTS * KNN * NPTS];  // [b][p][k][n]
__device__ int   g_pti[(size_t)BATCH * PARTS * KNN * NPTS];

// ---------------------------------------------------------------------------
// Kernel A: per-point projections + BN folding + ||x||^2  (unchanged, 48us)
// ---------------------------------------------------------------------------
__global__ void __launch_bounds__(128) prep_kernel(
    const float* __restrict__ x, const float* __restrict__ W,
    const float* __restrict__ gamma, const float* __restrict__ beta,
    const float* __restrict__ rmean, const float* __restrict__ rvar)
{
    __shared__ float sW[COUT * 2 * CIN];   // 64 x 128
    __shared__ float sA[COUT], sC0[COUT];

    const int t = threadIdx.x;
    const int b = blockIdx.y;
    const int n = blockIdx.x * 128 + t;

    for (int i = t; i < 2048; i += 128)
        ((float4*)sW)[i] = ((const float4*)W)[i];
    if (t < COUT) {
        float a = rsqrtf(rvar[t] + 1e-5f) * gamma[t];
        sA[t] = a;
        sC0[t] = fmaf(-a, rmean[t], beta[t]);
    }
    __syncthreads();

    const float* xb = x + (size_t)b * CIN * NPTS;
    float xq[CIN];
#pragma unroll
    for (int c = 0; c < CIN; c++) xq[c] = xb[(size_t)c * NPTS + n];

    float xx = 0.f;
#pragma unroll
    for (int c = 0; c < CIN; c++) xx = fmaf(xq[c], xq[c], xx);
    g_xx[(size_t)b * NPTS + n] = xx;

    float* y2r = g_y2p + ((size_t)b * NPTS + n) * COUT;
    float* zr  = g_zp  + ((size_t)b * NPTS + n) * COUT;

#pragma unroll 1
    for (int o = 0; o < COUT; o++) {
        const float* wr = sW + o * 128;
        float s2 = 0.f, sz = 0.f;
#pragma unroll
        for (int c = 0; c < 16; c++) {
            float4 w1 = *(const float4*)(wr + c * 4);
            float4 w2 = *(const float4*)(wr + 64 + c * 4);
            float q0 = xq[4*c+0], q1 = xq[4*c+1], q2 = xq[4*c+2], q3 = xq[4*c+3];
            s2 = fmaf(q0, w2.x, s2); sz = fmaf(q0, w1.x - w2.x, sz);
            s2 = fmaf(q1, w2.y, s2); sz = fmaf(q1, w1.y - w2.y, sz);
            s2 = fmaf(q2, w2.z, s2); sz = fmaf(q2, w1.z - w2.z, sz);
            s2 = fmaf(q3, w2.w, s2); sz = fmaf(q3, w1.w - w2.w, sz);
        }
        float a = sA[o];
        y2r[o] = a * s2;
        zr[o]  = fmaf(a, sz, sC0[o]);
    }
}

// ---------------------------------------------------------------------------
// top-20 insertion: replace current max, rescan. Ascending-m scan with
// strict '<' reproduces lax.top_k lowest-index tiebreak.
// ---------------------------------------------------------------------------
__device__ __forceinline__ void insert20(float (&td)[KNN], int (&ti)[KNN],
                                         float& kmax, int& kpos,
                                         float d, int m)
{
#pragma unroll
    for (int k = 0; k < KNN; k++) {
        if (k == kpos) { td[k] = d; ti[k] = m; }
    }
    float mx = -1e30f; int mp = 0;
#pragma unroll
    for (int k = 0; k < KNN; k++) {
        if (td[k] > mx) { mx = td[k]; mp = k; }
    }
    kmax = mx; kpos = mp;
}

// ---------------------------------------------------------------------------
// Kernel B: EXACT R5 inner structure (known-good 1580us loop), with the
// candidate range split PARTS ways across blockIdx.y. Only changes vs R5:
// candidate base offset, NT=32, and the top-20 list spills to global
// (epilogue moved to merge kernel). grid 256 -> 512 blocks.
// ---------------------------------------------------------------------------
__global__ void __launch_bounds__(128) knn_part_kernel(
    const float* __restrict__ x)
{
    __shared__ float s_xm[TM][68];   // [m][c], padded stride
    __shared__ float s_xx[TM];

    const int t = threadIdx.x;
    const int p = blockIdx.y;
    const int b = blockIdx.z;
    const int n = blockIdx.x * TN + t;
    const int cbase = p * PCAND;
    const float* xb = x + (size_t)b * CIN * NPTS;

    // query row in registers
    float xq[CIN];
#pragma unroll
    for (int c = 0; c < CIN; c++) xq[c] = xb[(size_t)c * NPTS + n];

    float xxq;
    {
        float s0 = 0.f, s1 = 0.f, s2 = 0.f, s3 = 0.f;
#pragma unroll
        for (int c = 0; c < CIN; c += 4) {
            s0 = fmaf(xq[c+0], xq[c+0], s0);
            s1 = fmaf(xq[c+1], xq[c+1], s1);
            s2 = fmaf(xq[c+2], xq[c+2], s2);
            s3 = fmaf(xq[c+3], xq[c+3], s3);
        }
        xxq = (s0 + s1) + (s2 + s3);
    }

    float td[KNN]; int ti[KNN];
#pragma unroll
    for (int k = 0; k < KNN; k++) { td[k] = 1e30f; ti[k] = 0; }
    float kmax = 1e30f; int kpos = 0;

    // cooperative tile loader mapping: thread -> (channel, half of m-range)
    const int lc = t >> 1;
    const int lm = (t & 1) * 32;
    const float* lptr = xb + (size_t)lc * NPTS + cbase + lm;
    const float* xxp  = g_xx + (size_t)b * NPTS + cbase;

    float4 ld[8]; float xld = 0.f;

    // prologue: tile 0 of this partition
#pragma unroll
    for (int j = 0; j < 8; j++) ld[j] = *(const float4*)(lptr + 4 * j);
    if (t < TM) xld = xxp[t];
#pragma unroll
    for (int j = 0; j < 8; j++) {
        int m = lm + 4 * j;
        s_xm[m+0][lc] = ld[j].x; s_xm[m+1][lc] = ld[j].y;
        s_xm[m+2][lc] = ld[j].z; s_xm[m+3][lc] = ld[j].w;
    }
    if (t < TM) s_xx[t] = xld;
    __syncthreads();

#pragma unroll 1
    for (int tile = 0; tile < NT; tile++) {
        // prefetch next tile into registers (latency hidden behind compute)
        if (tile + 1 < NT) {
            const float* pp = lptr + (tile + 1) * TM;
#pragma unroll
            for (int j = 0; j < 8; j++) ld[j] = *(const float4*)(pp + 4 * j);
            if (t < TM) xld = xxp[(tile + 1) * TM + t];
        }

        const int mbase = cbase + tile * TM;
#pragma unroll 1
        for (int mg = 0; mg < TM; mg += 4) {
            float a0 = 0.f, a1 = 0.f, a2 = 0.f, a3 = 0.f;
#pragma unroll
            for (int c4 = 0; c4 < 16; c4++) {
                const float4 v0 = *(const float4*)(&s_xm[mg+0][c4*4]);
                const float4 v1 = *(const float4*)(&s_xm[mg+1][c4*4]);
                const float4 v2 = *(const float4*)(&s_xm[mg+2][c4*4]);
                const float4 v3 = *(const float4*)(&s_xm[mg+3][c4*4]);
                const float q0 = xq[c4*4+0], q1 = xq[c4*4+1];
                const float q2 = xq[c4*4+2], q3 = xq[c4*4+3];
                a0 = fmaf(q0, v0.x, a0); a1 = fmaf(q0, v1.x, a1);
                a2 = fmaf(q0, v2.x, a2); a3 = fmaf(q0, v3.x, a3);
                a0 = fmaf(q1, v0.y, a0); a1 = fmaf(q1, v1.y, a1);
                a2 = fmaf(q1, v2.y, a2); a3 = fmaf(q1, v3.y, a3);
                a0 = fmaf(q2, v0.z, a0); a1 = fmaf(q2, v1.z, a1);
                a2 = fmaf(q2, v2.z, a2); a3 = fmaf(q2, v3.z, a3);
                a0 = fmaf(q3, v0.w, a0); a1 = fmaf(q3, v1.w, a1);
                a2 = fmaf(q3, v2.w, a2); a3 = fmaf(q3, v3.w, a3);
            }
            const float e0 = fmaf(a0, -2.f, xxq + s_xx[mg+0]);
            const float e1 = fmaf(a1, -2.f, xxq + s_xx[mg+1]);
            const float e2 = fmaf(a2, -2.f, xxq + s_xx[mg+2]);
            const float e3 = fmaf(a3, -2.f, xxq + s_xx[mg+3]);
            const float emin = fminf(fminf(e0, e1), fminf(e2, e3));
            if (emin < kmax) {
                if (e0 < kmax) insert20(td, ti, kmax, kpos, e0, mbase + mg + 0);
                if (e1 < kmax) insert20(td, ti, kmax, kpos, e1, mbase + mg + 1);
                if (e2 < kmax) insert20(td, ti, kmax, kpos, e2, mbase + mg + 2);
                if (e3 < kmax) insert20(td, ti, kmax, kpos, e3, mbase + mg + 3);
            }
        }
        __syncthreads();
        if (tile + 1 < NT) {
#pragma unroll
            for (int j = 0; j < 8; j++) {
                int m = lm + 4 * j;
                s_xm[m+0][lc] = ld[j].x; s_xm[m+1][lc] = ld[j].y;
                s_xm[m+2][lc] = ld[j].z; s_xm[m+3][lc] = ld[j].w;
            }
            if (t < TM) s_xx[t] = xld;
        }
        __syncthreads();
    }

    // store partition-local top-20, coalesced over n
    float* tdo = g_ptd + (size_t)(b * PARTS + p) * KNN * NPTS + n;
    int*   tio = g_pti + (size_t)(b * PARTS + p) * KNN * NPTS + n;
#pragma unroll
    for (int k = 0; k < KNN; k++) {
        tdo[(size_t)k * NPTS] = td[k];
        tio[(size_t)k * NPTS] = ti[k];
    }
}

// ---------------------------------------------------------------------------
// Kernel C: merge partition lists (ascending partition order preserves
// lowest-index tie-break; validated in R8 at rel_err 2.19e-7) +
// fused gather-max + BN/leaky epilogue (R5's epilogue verbatim).
// ---------------------------------------------------------------------------
__global__ void __launch_bounds__(128) merge_kernel(float* __restrict__ out)
{
    const int t = threadIdx.x;
    const int b = blockIdx.y;
    const int n = blockIdx.x * 128 + t;

    const float* tdp = g_ptd + (size_t)b * PARTS * KNN * NPTS + n;
    const int*   tip = g_pti + (size_t)b * PARTS * KNN * NPTS + n;

    float td[KNN]; int ti[KNN];
#pragma unroll
    for (int k = 0; k < KNN; k++) {
        td[k] = tdp[(size_t)k * NPTS];
        ti[k] = tip[(size_t)k * NPTS];
    }
    float kmax = -1e30f; int kpos = 0;
#pragma unroll
    for (int k = 0; k < KNN; k++) {
        if (td[k] > kmax) { kmax = td[k]; kpos = k; }
    }

#pragma unroll 1
    for (int p = 1; p < PARTS; p++) {
        const float* tdq = tdp + (size_t)p * KNN * NPTS;
        const int*   tiq = tip + (size_t)p * KNN * NPTS;
#pragma unroll
        for (int k = 0; k < KNN; k++) {
            float d = tdq[(size_t)k * NPTS];
            if (d < kmax) {
                int m = tiq[(size_t)k * NPTS];
                insert20(td, ti, kmax, kpos, d, m);
            }
        }
    }

    // out[b][o][n] = leaky(zp[n][o] + max_k y2p[idx_k][o])
    const float* y2b = g_y2p + (size_t)b * NPTS * COUT;
    float4 acc[16];
#pragma unroll
    for (int j = 0; j < 16; j++) acc[j] = make_float4(-1e30f, -1e30f, -1e30f, -1e30f);

#pragma unroll
    for (int k = 0; k < KNN; k++) {
        const float4* row = (const float4*)(y2b + (size_t)ti[k] * COUT);
#pragma unroll
        for (int j = 0; j < 16; j++) {
            float4 v = row[j];
            acc[j].x = fmaxf(acc[j].x, v.x);
            acc[j].y = fmaxf(acc[j].y, v.y);
            acc[j].z = fmaxf(acc[j].z, v.z);
            acc[j].w = fmaxf(acc[j].w, v.w);
        }
    }

    const float4* zr = (const float4*)(g_zp + ((size_t)b * NPTS + n) * COUT);
    float* ob = out + (size_t)b * COUT * NPTS + n;
#pragma unroll
    for (int j = 0; j < 16; j++) {
        float4 z = zr[j];
        float r0 = z.x + acc[j].x; r0 = (r0 >= 0.f) ? r0 : 0.2f * r0;
        float r1 = z.y + acc[j].y; r1 = (r1 >= 0.f) ? r1 : 0.2f * r1;
        float r2 = z.z + acc[j].z; r2 = (r2 >= 0.f) ? r2 : 0.2f * r2;
        float r3 = z.w + acc[j].w; r3 = (r3 >= 0.f) ? r3 : 0.2f * r3;
        ob[(size_t)(4*j+0) * NPTS] = r0;
        ob[(size_t)(4*j+1) * NPTS] = r1;
        ob[(size_t)(4*j+2) * NPTS] = r2;
        ob[(size_t)(4*j+3) * NPTS] = r3;
    }
}

// ---------------------------------------------------------------------------
extern "C" void kernel_launch(void* const* d_in, const int* in_sizes, int n_in,
                              void* d_out, int out_size)
{
    const float* x     = (const float*)d_in[0];
    const float* W     = (const float*)d_in[1];
    const float* gamma = (const float*)d_in[2];
    const float* beta  = (const float*)d_in[3];
    const float* rmean = (const float*)d_in[4];
    const float* rvar  = (const float*)d_in[5];
    float* out = (float*)d_out;

    (void)in_sizes; (void)n_in; (void)out_size;

    prep_kernel<<<dim3(NPTS / 128, BATCH), 128>>>(x, W, gamma, beta, rmean, rvar);
    knn_part_kernel<<<dim3(NPTS / TN, PARTS, BATCH), 128>>>(x);
    merge_kernel<<<dim3(NPTS / 128, BATCH), 128>>>(out);
}

// round 10
// speedup vs baseline: 2.9422x; 1.5373x over previous
#include <cuda_runtime.h>
#include <cstddef>
#include <cstdint>

#define BATCH 8
#define CIN 64
#define NPTS 4096
#define COUT 64
#define KNN 20
#define TM 64
#define QB 64                 // queries per block (x2 threads = 128)
#define NT (NPTS / TM)        // 64 tiles

// scratch (device globals: no allocations allowed)
__device__ float g_y2p[(size_t)BATCH * NPTS * COUT];  // a*(x . W2)
__device__ float g_zp [(size_t)BATCH * NPTS * COUT];  // a*(x . (W1-W2)) + beta - a*mean
__device__ float g_xx [(size_t)BATCH * NPTS];         // ||x_n||^2

// ---------------------------------------------------------------------------
// Kernel A: per-point projections + BN folding + ||x||^2  (unchanged, ~48us)
// ---------------------------------------------------------------------------
__global__ void __launch_bounds__(128) prep_kernel(
    const float* __restrict__ x, const float* __restrict__ W,
    const float* __restrict__ gamma, const float* __restrict__ beta,
    const float* __restrict__ rmean, const float* __restrict__ rvar)
{
    __shared__ float sW[COUT * 2 * CIN];   // 64 x 128
    __shared__ float sA[COUT], sC0[COUT];

    const int t = threadIdx.x;
    const int b = blockIdx.y;
    const int n = blockIdx.x * 128 + t;

    for (int i = t; i < 2048; i += 128)
        ((float4*)sW)[i] = ((const float4*)W)[i];
    if (t < COUT) {
        float a = rsqrtf(rvar[t] + 1e-5f) * gamma[t];
        sA[t] = a;
        sC0[t] = fmaf(-a, rmean[t], beta[t]);
    }
    __syncthreads();

    const float* xb = x + (size_t)b * CIN * NPTS;
    float xq[CIN];
#pragma unroll
    for (int c = 0; c < CIN; c++) xq[c] = xb[(size_t)c * NPTS + n];

    float xx = 0.f;
#pragma unroll
    for (int c = 0; c < CIN; c++) xx = fmaf(xq[c], xq[c], xx);
    g_xx[(size_t)b * NPTS + n] = xx;

    float* y2r = g_y2p + ((size_t)b * NPTS + n) * COUT;
    float* zr  = g_zp  + ((size_t)b * NPTS + n) * COUT;

#pragma unroll 1
    for (int o = 0; o < COUT; o++) {
        const float* wr = sW + o * 128;
        float s2 = 0.f, sz = 0.f;
#pragma unroll
        for (int c = 0; c < 16; c++) {
            float4 w1 = *(const float4*)(wr + c * 4);
            float4 w2 = *(const float4*)(wr + 64 + c * 4);
            float q0 = xq[4*c+0], q1 = xq[4*c+1], q2 = xq[4*c+2], q3 = xq[4*c+3];
            s2 = fmaf(q0, w2.x, s2); sz = fmaf(q0, w1.x - w2.x, sz);
            s2 = fmaf(q1, w2.y, s2); sz = fmaf(q1, w1.y - w2.y, sz);
            s2 = fmaf(q2, w2.z, s2); sz = fmaf(q2, w1.z - w2.z, sz);
            s2 = fmaf(q3, w2.w, s2); sz = fmaf(q3, w1.w - w2.w, sz);
        }
        float a = sA[o];
        y2r[o] = a * s2;
        zr[o]  = fmaf(a, sz, sC0[o]);
    }
}

// ---------------------------------------------------------------------------
// smem top-20 insertion: replace current max, rescan. Column stride QB keeps
// per-query lists bank-conflict-free (q maps to consecutive banks; pair lanes
// broadcast). Ascending-m scan + strict '<' = lax.top_k lowest-index tiebreak.
// ---------------------------------------------------------------------------
__device__ __forceinline__ void insert20s(float* __restrict__ tdc,
                                          int* __restrict__ tic,
                                          float& kmax, int& kpos,
                                          float d, int m)
{
    tdc[kpos * QB] = d;
    tic[kpos * QB] = m;
    float mx = -1e30f; int mp = 0;
#pragma unroll
    for (int k = 0; k < KNN; k++) {
        float v = tdc[k * QB];
        if (v > mx) { mx = v; mp = k; }
    }
    kmax = mx; kpos = mp;
}

// ---------------------------------------------------------------------------
// Kernel B: fused knn + epilogue, 2 threads per query (channel-split).
// Lane pair (2q, 2q+1) holds xq halves; shfl_xor(1) completes each dot with
// bit-identical sums on both lanes -> pair stays in lockstep through the
// divergent insert path. Top-20 lists live in smem (frees 40 regs); xq is 32
// regs (frees 32) -> target 3 blocks/SM at grid 512 (R5 was 255 regs, 2
// blocks, grid 256 -> 6.9 warps/SM; this aims for ~12).
// ---------------------------------------------------------------------------
__global__ void __launch_bounds__(128) knn_fused_kernel(
    const float* __restrict__ x, float* __restrict__ out)
{
    __shared__ float s_xm[TM][68];     // [m][c] candidate tile, padded
    __shared__ float s_xx[TM];
    __shared__ float s_td[KNN][QB];    // per-query top-20 distances
    __shared__ int   s_ti[KNN][QB];    // per-query top-20 indices

    const int t    = threadIdx.x;
    const int q    = t >> 1;           // local query 0..63
    const int half = t & 1;            // channel half
    const int b    = blockIdx.y;
    const int n    = blockIdx.x * QB + q;
    const float* xb = x + (size_t)b * CIN * NPTS;

    // this lane's half of the query row (32 channels)
    float xq[32];
#pragma unroll
    for (int c = 0; c < 32; c++)
        xq[c] = xb[(size_t)(half * 32 + c) * NPTS + n];

    const float xxq = g_xx[(size_t)b * NPTS + n];

    // init top-k (pair lanes write identical values)
    float* tdc = &s_td[0][q];
    int*   tic = &s_ti[0][q];
#pragma unroll
    for (int k = 0; k < KNN; k++) { tdc[k * QB] = 1e30f; tic[k * QB] = 0; }
    float kmax = 1e30f; int kpos = 0;

    // cooperative tile loader (same mapping as R5: channel = t>>1, m-half = t&1)
    const int lc = t >> 1;
    const int lm = (t & 1) * 32;
    const float* lptr = xb + (size_t)lc * NPTS + lm;
    const float* xxp  = g_xx + (size_t)b * NPTS;

    float4 ld[8]; float xld = 0.f;

    // prologue: tile 0
#pragma unroll
    for (int j = 0; j < 8; j++) ld[j] = *(const float4*)(lptr + 4 * j);
    if (t < TM) xld = xxp[t];
#pragma unroll
    for (int j = 0; j < 8; j++) {
        int m = lm + 4 * j;
        s_xm[m+0][lc] = ld[j].x; s_xm[m+1][lc] = ld[j].y;
        s_xm[m+2][lc] = ld[j].z; s_xm[m+3][lc] = ld[j].w;
    }
    if (t < TM) s_xx[t] = xld;
    __syncthreads();

    const int coff = half * 32;        // this lane's channel window in the tile

#pragma unroll 1
    for (int tile = 0; tile < NT; tile++) {
        // prefetch next tile into registers
        if (tile + 1 < NT) {
            const float* pp = lptr + (tile + 1) * TM;
#pragma unroll
            for (int j = 0; j < 8; j++) ld[j] = *(const float4*)(pp + 4 * j);
            if (t < TM) xld = xxp[(tile + 1) * TM + t];
        }

        const int mbase = tile * TM;
#pragma unroll 1
        for (int mg = 0; mg < TM; mg += 4) {
            float a0 = 0.f, a1 = 0.f, a2 = 0.f, a3 = 0.f;
#pragma unroll
            for (int c4 = 0; c4 < 8; c4++) {        // 8 x 4 = 32 channels
                const float4 v0 = *(const float4*)(&s_xm[mg+0][coff + c4*4]);
                const float4 v1 = *(const float4*)(&s_xm[mg+1][coff + c4*4]);
                const float4 v2 = *(const float4*)(&s_xm[mg+2][coff + c4*4]);
                const float4 v3 = *(const float4*)(&s_xm[mg+3][coff + c4*4]);
                const float q0 = xq[c4*4+0], q1 = xq[c4*4+1];
                const float q2 = xq[c4*4+2], q3 = xq[c4*4+3];
                a0 = fmaf(q0, v0.x, a0); a1 = fmaf(q0, v1.x, a1);
                a2 = fmaf(q0, v2.x, a2); a3 = fmaf(q0, v3.x, a3);
                a0 = fmaf(q1, v0.y, a0); a1 = fmaf(q1, v1.y, a1);
                a2 = fmaf(q1, v2.y, a2); a3 = fmaf(q1, v3.y, a3);
                a0 = fmaf(q2, v0.z, a0); a1 = fmaf(q2, v1.z, a1);
                a2 = fmaf(q2, v2.z, a2); a3 = fmaf(q2, v3.z, a3);
                a0 = fmaf(q3, v0.w, a0); a1 = fmaf(q3, v1.w, a1);
                a2 = fmaf(q3, v2.w, a2); a3 = fmaf(q3, v3.w, a3);
            }
            // combine channel halves: both lanes get bit-identical full sums
            a0 += __shfl_xor_sync(0xffffffffu, a0, 1);
            a1 += __shfl_xor_sync(0xffffffffu, a1, 1);
            a2 += __shfl_xor_sync(0xffffffffu, a2, 1);
            a3 += __shfl_xor_sync(0xffffffffu, a3, 1);

            const float e0 = fmaf(a0, -2.f, xxq + s_xx[mg+0]);
            const float e1 = fmaf(a1, -2.f, xxq + s_xx[mg+1]);
            const float e2 = fmaf(a2, -2.f, xxq + s_xx[mg+2]);
            const float e3 = fmaf(a3, -2.f, xxq + s_xx[mg+3]);
            const float emin = fminf(fminf(e0, e1), fminf(e2, e3));
            if (emin < kmax) {
                if (e0 < kmax) insert20s(tdc, tic, kmax, kpos, e0, mbase + mg + 0);
                if (e1 < kmax) insert20s(tdc, tic, kmax, kpos, e1, mbase + mg + 1);
                if (e2 < kmax) insert20s(tdc, tic, kmax, kpos, e2, mbase + mg + 2);
                if (e3 < kmax) insert20s(tdc, tic, kmax, kpos, e3, mbase + mg + 3);
            }
        }
        __syncthreads();
        if (tile + 1 < NT) {
#pragma unroll
            for (int j = 0; j < 8; j++) {
                int m = lm + 4 * j;
                s_xm[m+0][lc] = ld[j].x; s_xm[m+1][lc] = ld[j].y;
                s_xm[m+2][lc] = ld[j].z; s_xm[m+3][lc] = ld[j].w;
            }
            if (t < TM) s_xx[t] = xld;
        }
        __syncthreads();
    }

    // ---- fused epilogue: each lane covers its 32 output channels of query q
    // out[b][o][n] = leaky(zp[n][o] + max_k y2p[idx_k][o])
    const float* y2b = g_y2p + (size_t)b * NPTS * COUT + coff;
    float4 acc[8];
#pragma unroll
    for (int j = 0; j < 8; j++) acc[j] = make_float4(-1e30f, -1e30f, -1e30f, -1e30f);

#pragma unroll
    for (int k = 0; k < KNN; k++) {
        const int m = tic[k * QB];
        const float4* row = (const float4*)(y2b + (size_t)m * COUT);
#pragma unroll
        for (int j = 0; j < 8; j++) {
            float4 v = row[j];
            acc[j].x = fmaxf(acc[j].x, v.x);
            acc[j].y = fmaxf(acc[j].y, v.y);
            acc[j].z = fmaxf(acc[j].z, v.z);
            acc[j].w = fmaxf(acc[j].w, v.w);
        }
    }

    const float4* zr = (const float4*)(g_zp + ((size_t)b * NPTS + n) * COUT + coff);
    float* ob = out + (size_t)b * COUT * NPTS + (size_t)coff * NPTS + n;
#pragma unroll
    for (int j = 0; j < 8; j++) {
        float4 z = zr[j];
        float r0 = z.x + acc[j].x; r0 = (r0 >= 0.f) ? r0 : 0.2f * r0;
        float r1 = z.y + acc[j].y; r1 = (r1 >= 0.f) ? r1 : 0.2f * r1;
        float r2 = z.z + acc[j].z; r2 = (r2 >= 0.f) ? r2 : 0.2f * r2;
        float r3 = z.w + acc[j].w; r3 = (r3 >= 0.f) ? r3 : 0.2f * r3;
        ob[(size_t)(4*j+0) * NPTS] = r0;
        ob[(size_t)(4*j+1) * NPTS] = r1;
        ob[(size_t)(4*j+2) * NPTS] = r2;
        ob[(size_t)(4*j+3) * NPTS] = r3;
    }
}

// ---------------------------------------------------------------------------
extern "C" void kernel_launch(void* const* d_in, const int* in_sizes, int n_in,
                              void* d_out, int out_size)
{
    const float* x     = (const float*)d_in[0];
    const float* W     = (const float*)d_in[1];
    const float* gamma = (const float*)d_in[2];
    const float* beta  = (const float*)d_in[3];
    const float* rmean = (const float*)d_in[4];
    const float* rvar  = (const float*)d_in[5];
    float* out = (float*)d_out;

    (void)in_sizes; (void)n_in; (void)out_size;

    prep_kernel<<<dim3(NPTS / 128, BATCH), 128>>>(x, W, gamma, beta, rmean, rvar);
    knn_fused_kernel<<<dim3(NPTS / QB, BATCH), 128>>>(x, out);
}

// round 11
// speedup vs baseline: 3.4333x; 1.1669x over previous
#include <cuda_runtime.h>
#include <cstddef>
#include <cstdint>

#define BATCH 8
#define CIN 64
#define NPTS 4096
#define COUT 64
#define KNN 20
#define TM 64
#define QB 128                 // queries per block (2 per lane-pair)
#define PARTS 2
#define PCAND (NPTS / PARTS)   // 2048 candidates per partition
#define NT (PCAND / TM)        // 32 tiles

// scratch (device globals: no allocations allowed)
__device__ float g_y2p[(size_t)BATCH * NPTS * COUT];  // a*(x . W2)
__device__ float g_zp [(size_t)BATCH * NPTS * COUT];  // a*(x . (W1-W2)) + beta - a*mean
__device__ float g_xx [(size_t)BATCH * NPTS];         // ||x_n||^2
__device__ float g_ptd[(size_t)BATCH * PARTS * KNN * NPTS];  // [b][p][k][n]
__device__ int   g_pti[(size_t)BATCH * PARTS * KNN * NPTS];

// ---------------------------------------------------------------------------
// Kernel A: per-point projections + BN folding + ||x||^2  (unchanged, ~48us)
// ---------------------------------------------------------------------------
__global__ void __launch_bounds__(128) prep_kernel(
    const float* __restrict__ x, const float* __restrict__ W,
    const float* __restrict__ gamma, const float* __restrict__ beta,
    const float* __restrict__ rmean, const float* __restrict__ rvar)
{
    __shared__ float sW[COUT * 2 * CIN];   // 64 x 128
    __shared__ float sA[COUT], sC0[COUT];

    const int t = threadIdx.x;
    const int b = blockIdx.y;
    const int n = blockIdx.x * 128 + t;

    for (int i = t; i < 2048; i += 128)
        ((float4*)sW)[i] = ((const float4*)W)[i];
    if (t < COUT) {
        float a = rsqrtf(rvar[t] + 1e-5f) * gamma[t];
        sA[t] = a;
        sC0[t] = fmaf(-a, rmean[t], beta[t]);
    }
    __syncthreads();

    const float* xb = x + (size_t)b * CIN * NPTS;
    float xq[CIN];
#pragma unroll
    for (int c = 0; c < CIN; c++) xq[c] = xb[(size_t)c * NPTS + n];

    float xx = 0.f;
#pragma unroll
    for (int c = 0; c < CIN; c++) xx = fmaf(xq[c], xq[c], xx);
    g_xx[(size_t)b * NPTS + n] = xx;

    float* y2r = g_y2p + ((size_t)b * NPTS + n) * COUT;
    float* zr  = g_zp  + ((size_t)b * NPTS + n) * COUT;

#pragma unroll 1
    for (int o = 0; o < COUT; o++) {
        const float* wr = sW + o * 128;
        float s2 = 0.f, sz = 0.f;
#pragma unroll
        for (int c = 0; c < 16; c++) {
            float4 w1 = *(const float4*)(wr + c * 4);
            float4 w2 = *(const float4*)(wr + 64 + c * 4);
            float q0 = xq[4*c+0], q1 = xq[4*c+1], q2 = xq[4*c+2], q3 = xq[4*c+3];
            s2 = fmaf(q0, w2.x, s2); sz = fmaf(q0, w1.x - w2.x, sz);
            s2 = fmaf(q1, w2.y, s2); sz = fmaf(q1, w1.y - w2.y, sz);
            s2 = fmaf(q2, w2.z, s2); sz = fmaf(q2, w1.z - w2.z, sz);
            s2 = fmaf(q3, w2.w, s2); sz = fmaf(q3, w1.w - w2.w, sz);
        }
        float a = sA[o];
        y2r[o] = a * s2;
        zr[o]  = fmaf(a, sz, sC0[o]);
    }
}

// ---------------------------------------------------------------------------
// smem top-20 insertion: replace current max, rescan. Column stride QB.
// Ascending-m scan + strict '<' = lax.top_k lowest-index tiebreak.
// ---------------------------------------------------------------------------
__device__ __forceinline__ void insert20s(float* __restrict__ tdc,
                                          int* __restrict__ tic,
                                          float& kmax, int& kpos,
                                          float d, int m)
{
    tdc[kpos * QB] = d;
    tic[kpos * QB] = m;
    float mx = -1e30f; int mp = 0;
#pragma unroll
    for (int k = 0; k < KNN; k++) {
        float v = tdc[k * QB];
        if (v > mx) { mx = v; mp = k; }
    }
    kmax = mx; kpos = mp;
}

// ---------------------------------------------------------------------------
// Kernel B: knn with 2 queries per lane-pair (channel-split), PARTS=2.
// Each candidate float4 loaded from smem feeds BOTH queries' FMAs ->
// 2.0 FMA per loaded float (R10 was 1.0; L1-return was the 82% bottleneck).
// Lane pair (2i,2i+1) holds channel halves of local queries 2i and 2i+1;
// shfl_xor(1) gives both lanes bit-identical full sums -> lockstep inserts.
// Partition-local top-20 spills to global; merge kernel does the epilogue.
// ---------------------------------------------------------------------------
__global__ void __launch_bounds__(128) knn_part_kernel(
    const float* __restrict__ x)
{
    __shared__ float s_xm[TM][68];     // [m][c] candidate tile, padded
    __shared__ float s_xx[TM];
    __shared__ float s_td[KNN][QB];    // per-query top-20 distances
    __shared__ int   s_ti[KNN][QB];    // per-query top-20 indices

    const int t    = threadIdx.x;
    const int pair = t >> 1;           // 0..63
    const int half = t & 1;            // channel half
    const int p    = blockIdx.y;
    const int b    = blockIdx.z;
    const int qa   = 2 * pair;         // local query A
    const int qb   = qa + 1;           // local query B
    const int na   = blockIdx.x * QB + qa;
    const int nb   = na + 1;
    const int cbase = p * PCAND;
    const float* xb = x + (size_t)b * CIN * NPTS;

    // channel-half of two query rows (32+32 regs)
    float xqa[32], xqb[32];
#pragma unroll
    for (int c = 0; c < 32; c++) {
        xqa[c] = xb[(size_t)(half * 32 + c) * NPTS + na];
        xqb[c] = xb[(size_t)(half * 32 + c) * NPTS + nb];
    }
    const float xxqa = g_xx[(size_t)b * NPTS + na];
    const float xxqb = g_xx[(size_t)b * NPTS + nb];

    // init both top-k lists (pair lanes write identical values — benign)
    float* tda = &s_td[0][qa]; int* tia = &s_ti[0][qa];
    float* tdb = &s_td[0][qb]; int* tib = &s_ti[0][qb];
#pragma unroll
    for (int k = 0; k < KNN; k++) {
        tda[k * QB] = 1e30f; tia[k * QB] = 0;
        tdb[k * QB] = 1e30f; tib[k * QB] = 0;
    }
    float kmaxa = 1e30f; int kposa = 0;
    float kmaxb = 1e30f; int kposb = 0;

    // cooperative tile loader (R5/R10 mapping)
    const int lc = t >> 1;
    const int lm = (t & 1) * 32;
    const float* lptr = xb + (size_t)lc * NPTS + cbase + lm;
    const float* xxp  = g_xx + (size_t)b * NPTS + cbase;

    float4 ld[8]; float xld = 0.f;

    // prologue: tile 0
#pragma unroll
    for (int j = 0; j < 8; j++) ld[j] = *(const float4*)(lptr + 4 * j);
    if (t < TM) xld = xxp[t];
#pragma unroll
    for (int j = 0; j < 8; j++) {
        int m = lm + 4 * j;
        s_xm[m+0][lc] = ld[j].x; s_xm[m+1][lc] = ld[j].y;
        s_xm[m+2][lc] = ld[j].z; s_xm[m+3][lc] = ld[j].w;
    }
    if (t < TM) s_xx[t] = xld;
    __syncthreads();

    const int coff = half * 32;        // this lane's channel window

#pragma unroll 1
    for (int tile = 0; tile < NT; tile++) {
        // prefetch next tile into registers
        if (tile + 1 < NT) {
            const float* pp = lptr + (tile + 1) * TM;
#pragma unroll
            for (int j = 0; j < 8; j++) ld[j] = *(const float4*)(pp + 4 * j);
            if (t < TM) xld = xxp[(tile + 1) * TM + t];
        }

        const int mbase = cbase + tile * TM;
#pragma unroll 1
        for (int mg = 0; mg < TM; mg += 4) {
            float a0 = 0.f, a1 = 0.f, a2 = 0.f, a3 = 0.f;   // query A
            float b0 = 0.f, b1 = 0.f, b2 = 0.f, b3 = 0.f;   // query B
#pragma unroll
            for (int c4 = 0; c4 < 8; c4++) {   // 32 channels per lane
                const float4 v0 = *(const float4*)(&s_xm[mg+0][coff + c4*4]);
                const float4 v1 = *(const float4*)(&s_xm[mg+1][coff + c4*4]);
                const float4 v2 = *(const float4*)(&s_xm[mg+2][coff + c4*4]);
                const float4 v3 = *(const float4*)(&s_xm[mg+3][coff + c4*4]);
                const float qa0 = xqa[c4*4+0], qa1 = xqa[c4*4+1];
                const float qa2 = xqa[c4*4+2], qa3 = xqa[c4*4+3];
                const float qb0 = xqb[c4*4+0], qb1 = xqb[c4*4+1];
                const float qb2 = xqb[c4*4+2], qb3 = xqb[c4*4+3];
                a0 = fmaf(qa0, v0.x, a0); b0 = fmaf(qb0, v0.x, b0);
                a1 = fmaf(qa0, v1.x, a1); b1 = fmaf(qb0, v1.x, b1);
                a2 = fmaf(qa0, v2.x, a2); b2 = fmaf(qb0, v2.x, b2);
                a3 = fmaf(qa0, v3.x, a3); b3 = fmaf(qb0, v3.x, b3);
                a0 = fmaf(qa1, v0.y, a0); b0 = fmaf(qb1, v0.y, b0);
                a1 = fmaf(qa1, v1.y, a1); b1 = fmaf(qb1, v1.y, b1);
                a2 = fmaf(qa1, v2.y, a2); b2 = fmaf(qb1, v2.y, b2);
                a3 = fmaf(qa1, v3.y, a3); b3 = fmaf(qb1, v3.y, b3);
                a0 = fmaf(qa2, v0.z, a0); b0 = fmaf(qb2, v0.z, b0);
                a1 = fmaf(qa2, v1.z, a1); b1 = fmaf(qb2, v1.z, b1);
                a2 = fmaf(qa2, v2.z, a2); b2 = fmaf(qb2, v2.z, b2);
                a3 = fmaf(qa2, v3.z, a3); b3 = fmaf(qb2, v3.z, b3);
                a0 = fmaf(qa3, v0.w, a0); b0 = fmaf(qb3, v0.w, b0);
                a1 = fmaf(qa3, v1.w, a1); b1 = fmaf(qb3, v1.w, b1);
                a2 = fmaf(qa3, v2.w, a2); b2 = fmaf(qb3, v2.w, b2);
                a3 = fmaf(qa3, v3.w, a3); b3 = fmaf(qb3, v3.w, b3);
            }
            // combine channel halves: bit-identical sums on both lanes
            a0 += __shfl_xor_sync(0xffffffffu, a0, 1);
            a1 += __shfl_xor_sync(0xffffffffu, a1, 1);
            a2 += __shfl_xor_sync(0xffffffffu, a2, 1);
            a3 += __shfl_xor_sync(0xffffffffu, a3, 1);
            b0 += __shfl_xor_sync(0xffffffffu, b0, 1);
            b1 += __shfl_xor_sync(0xffffffffu, b1, 1);
            b2 += __shfl_xor_sync(0xffffffffu, b2, 1);
            b3 += __shfl_xor_sync(0xffffffffu, b3, 1);

            const float sx0 = s_xx[mg+0], sx1 = s_xx[mg+1];
            const float sx2 = s_xx[mg+2], sx3 = s_xx[mg+3];

            const float ea0 = fmaf(a0, -2.f, xxqa + sx0);
            const float ea1 = fmaf(a1, -2.f, xxqa + sx1);
            const float ea2 = fmaf(a2, -2.f, xxqa + sx2);
            const float ea3 = fmaf(a3, -2.f, xxqa + sx3);
            const float emina = fminf(fminf(ea0, ea1), fminf(ea2, ea3));
            if (emina < kmaxa) {
                if (ea0 < kmaxa) insert20s(tda, tia, kmaxa, kposa, ea0, mbase + mg + 0);
                if (ea1 < kmaxa) insert20s(tda, tia, kmaxa, kposa, ea1, mbase + mg + 1);
                if (ea2 < kmaxa) insert20s(tda, tia, kmaxa, kposa, ea2, mbase + mg + 2);
                if (ea3 < kmaxa) insert20s(tda, tia, kmaxa, kposa, ea3, mbase + mg + 3);
            }

            const float eb0 = fmaf(b0, -2.f, xxqb + sx0);
            const float eb1 = fmaf(b1, -2.f, xxqb + sx1);
            const float eb2 = fmaf(b2, -2.f, xxqb + sx2);
            const float eb3 = fmaf(b3, -2.f, xxqb + sx3);
            const float eminb = fminf(fminf(eb0, eb1), fminf(eb2, eb3));
            if (eminb < kmaxb) {
                if (eb0 < kmaxb) insert20s(tdb, tib, kmaxb, kposb, eb0, mbase + mg + 0);
                if (eb1 < kmaxb) insert20s(tdb, tib, kmaxb, kposb, eb1, mbase + mg + 1);
                if (eb2 < kmaxb) insert20s(tdb, tib, kmaxb, kposb, eb2, mbase + mg + 2);
                if (eb3 < kmaxb) insert20s(tdb, tib, kmaxb, kposb, eb3, mbase + mg + 3);
            }
        }
        __syncthreads();
        if (tile + 1 < NT) {
#pragma unroll
            for (int j = 0; j < 8; j++) {
                int m = lm + 4 * j;
                s_xm[m+0][lc] = ld[j].x; s_xm[m+1][lc] = ld[j].y;
                s_xm[m+2][lc] = ld[j].z; s_xm[m+3][lc] = ld[j].w;
            }
            if (t < TM) s_xx[t] = xld;
        }
        __syncthreads();
    }

    // spill partition-local top-20 lists (thread t <-> list column t, coalesced)
    {
        const int n = blockIdx.x * QB + t;
        float* tdo = g_ptd + (size_t)(b * PARTS + p) * KNN * NPTS + n;
        int*   tio = g_pti + (size_t)(b * PARTS + p) * KNN * NPTS + n;
#pragma unroll
        for (int k = 0; k < KNN; k++) {
            tdo[(size_t)k * NPTS] = s_td[k][t];
            tio[(size_t)k * NPTS] = s_ti[k][t];
        }
    }
}

// ---------------------------------------------------------------------------
// Kernel C: merge partition lists (ascending partition order preserves
// lowest-index tie-break; validated R8/R9) + gather-max + BN/leaky epilogue.
// ---------------------------------------------------------------------------
__device__ __forceinline__ void insert20r(float (&td)[KNN], int (&ti)[KNN],
                                          float& kmax, int& kpos,
                                          float d, int m)
{
#pragma unroll
    for (int k = 0; k < KNN; k++) {
        if (k == kpos) { td[k] = d; ti[k] = m; }
    }
    float mx = -1e30f; int mp = 0;
#pragma unroll
    for (int k = 0; k < KNN; k++) {
        if (td[k] > mx) { mx = td[k]; mp = k; }
    }
    kmax = mx; kpos = mp;
}

__global__ void __launch_bounds__(128) merge_kernel(float* __restrict__ out)
{
    const int t = threadIdx.x;
    const int b = blockIdx.y;
    const int n = blockIdx.x * 128 + t;

    const float* tdp = g_ptd + (size_t)b * PARTS * KNN * NPTS + n;
    const int*   tip = g_pti + (size_t)b * PARTS * KNN * NPTS + n;

    float td[KNN]; int ti[KNN];
#pragma unroll
    for (int k = 0; k < KNN; k++) {
        td[k] = tdp[(size_t)k * NPTS];
        ti[k] = tip[(size_t)k * NPTS];
    }
    float kmax = -1e30f; int kpos = 0;
#pragma unroll
    for (int k = 0; k < KNN; k++) {
        if (td[k] > kmax) { kmax = td[k]; kpos = k; }
    }

#pragma unroll 1
    for (int p = 1; p < PARTS; p++) {
        const float* tdq = tdp + (size_t)p * KNN * NPTS;
        const int*   tiq = tip + (size_t)p * KNN * NPTS;
#pragma unroll
        for (int k = 0; k < KNN; k++) {
            float d = tdq[(size_t)k * NPTS];
            if (d < kmax) {
                int m = tiq[(size_t)k * NPTS];
                insert20r(td, ti, kmax, kpos, d, m);
            }
        }
    }

    // out[b][o][n] = leaky(zp[n][o] + max_k y2p[idx_k][o])
    const float* y2b = g_y2p + (size_t)b * NPTS * COUT;
    float4 acc[16];
#pragma unroll
    for (int j = 0; j < 16; j++) acc[j] = make_float4(-1e30f, -1e30f, -1e30f, -1e30f);

#pragma unroll
    for (int k = 0; k < KNN; k++) {
        const float4* row = (const float4*)(y2b + (size_t)ti[k] * COUT);
#pragma unroll
        for (int j = 0; j < 16; j++) {
            float4 v = row[j];
            acc[j].x = fmaxf(acc[j].x, v.x);
            acc[j].y = fmaxf(acc[j].y, v.y);
            acc[j].z = fmaxf(acc[j].z, v.z);
            acc[j].w = fmaxf(acc[j].w, v.w);
        }
    }

    const float4* zr = (const float4*)(g_zp + ((size_t)b * NPTS + n) * COUT);
    float* ob = out + (size_t)b * COUT * NPTS + n;
#pragma unroll
    for (int j = 0; j < 16; j++) {
        float4 z = zr[j];
        float r0 = z.x + acc[j].x; r0 = (r0 >= 0.f) ? r0 : 0.2f * r0;
        float r1 = z.y + acc[j].y; r1 = (r1 >= 0.f) ? r1 : 0.2f * r1;
        float r2 = z.z + acc[j].z; r2 = (r2 >= 0.f) ? r2 : 0.2f * r2;
        float r3 = z.w + acc[j].w; r3 = (r3 >= 0.f) ? r3 : 0.2f * r3;
        ob[(size_t)(4*j+0) * NPTS] = r0;
        ob[(size_t)(4*j+1) * NPTS] = r1;
        ob[(size_t)(4*j+2) * NPTS] = r2;
        ob[(size_t)(4*j+3) * NPTS] = r3;
    }
}

// ---------------------------------------------------------------------------
extern "C" void kernel_launch(void* const* d_in, const int* in_sizes, int n_in,
                              void* d_out, int out_size)
{
    const float* x     = (const float*)d_in[0];
    const float* W     = (const float*)d_in[1];
    const float* gamma = (const float*)d_in[2];
    const float* beta  = (const float*)d_in[3];
    const float* rmean = (const float*)d_in[4];
    const float* rvar  = (const float*)d_in[5];
    float* out = (float*)d_out;

    (void)in_sizes; (void)n_in; (void)out_size;

    prep_kernel<<<dim3(NPTS / 128, BATCH), 128>>>(x, W, gamma, beta, rmean, rvar);
    knn_part_kernel<<<dim3(NPTS / QB, PARTS, BATCH), 128>>>(x);
    merge_kernel<<<dim3(NPTS / 128, BATCH), 128>>>(out);
}

// round 12
// speedup vs baseline: 4.3088x; 1.2550x over previous
#include <cuda_runtime.h>
#include <cstddef>
#include <cstdint>

#define BATCH 8
#define CIN 64
#define NPTS 4096
#define COUT 64
#define KNN 20
#define TM 64
#define QB 128                 // queries per block (4 per lane-quad)
#define PARTS 2
#define PCAND (NPTS / PARTS)   // 2048 candidates per partition
#define NT (PCAND / TM)        // 32 tiles

// scratch (device globals: no allocations allowed)
__device__ float g_y2p[(size_t)BATCH * NPTS * COUT];  // a*(x . W2)
__device__ float g_zp [(size_t)BATCH * NPTS * COUT];  // a*(x . (W1-W2)) + beta - a*mean
__device__ float g_xx [(size_t)BATCH * NPTS];         // ||x_n||^2
__device__ float g_ptd[(size_t)BATCH * PARTS * KNN * NPTS];  // [b][p][k][n]
__device__ int   g_pti[(size_t)BATCH * PARTS * KNN * NPTS];

// ---------------------------------------------------------------------------
// Kernel A: per-point projections + BN folding + ||x||^2  (unchanged, ~48us)
// ---------------------------------------------------------------------------
__global__ void __launch_bounds__(128) prep_kernel(
    const float* __restrict__ x, const float* __restrict__ W,
    const float* __restrict__ gamma, const float* __restrict__ beta,
    const float* __restrict__ rmean, const float* __restrict__ rvar)
{
    __shared__ float sW[COUT * 2 * CIN];   // 64 x 128
    __shared__ float sA[COUT], sC0[COUT];

    const int t = threadIdx.x;
    const int b = blockIdx.y;
    const int n = blockIdx.x * 128 + t;

    for (int i = t; i < 2048; i += 128)
        ((float4*)sW)[i] = ((const float4*)W)[i];
    if (t < COUT) {
        float a = rsqrtf(rvar[t] + 1e-5f) * gamma[t];
        sA[t] = a;
        sC0[t] = fmaf(-a, rmean[t], beta[t]);
    }
    __syncthreads();

    const float* xb = x + (size_t)b * CIN * NPTS;
    float xq[CIN];
#pragma unroll
    for (int c = 0; c < CIN; c++) xq[c] = xb[(size_t)c * NPTS + n];

    float xx = 0.f;
#pragma unroll
    for (int c = 0; c < CIN; c++) xx = fmaf(xq[c], xq[c], xx);
    g_xx[(size_t)b * NPTS + n] = xx;

    float* y2r = g_y2p + ((size_t)b * NPTS + n) * COUT;
    float* zr  = g_zp  + ((size_t)b * NPTS + n) * COUT;

#pragma unroll 1
    for (int o = 0; o < COUT; o++) {
        const float* wr = sW + o * 128;
        float s2 = 0.f, sz = 0.f;
#pragma unroll
        for (int c = 0; c < 16; c++) {
            float4 w1 = *(const float4*)(wr + c * 4);
            float4 w2 = *(const float4*)(wr + 64 + c * 4);
            float q0 = xq[4*c+0], q1 = xq[4*c+1], q2 = xq[4*c+2], q3 = xq[4*c+3];
            s2 = fmaf(q0, w2.x, s2); sz = fmaf(q0, w1.x - w2.x, sz);
            s2 = fmaf(q1, w2.y, s2); sz = fmaf(q1, w1.y - w2.y, sz);
            s2 = fmaf(q2, w2.z, s2); sz = fmaf(q2, w1.z - w2.z, sz);
            s2 = fmaf(q3, w2.w, s2); sz = fmaf(q3, w1.w - w2.w, sz);
        }
        float a = sA[o];
        y2r[o] = a * s2;
        zr[o]  = fmaf(a, sz, sC0[o]);
    }
}

// ---------------------------------------------------------------------------
// smem top-20 insertion: replace current max, rescan. Column stride QB keeps
// lanes on distinct banks (QB=128 ≡ 0 mod 32). Ascending-m scan with strict
// '<' reproduces lax.top_k lowest-index tiebreak.
// ---------------------------------------------------------------------------
__device__ __forceinline__ void insert20s(float* __restrict__ tdc,
                                          int* __restrict__ tic,
                                          float& kmax, int& kpos,
                                          float d, int m)
{
    tdc[kpos * QB] = d;
    tic[kpos * QB] = m;
    float mx = -1e30f; int mp = 0;
#pragma unroll
    for (int k = 0; k < KNN; k++) {
        float v = tdc[k * QB];
        if (v > mx) { mx = v; mp = k; }
    }
    kmax = mx; kpos = mp;
}

// ---------------------------------------------------------------------------
// Kernel B: knn, 4 queries per lane-quad, interleaved channel windows.
// Lane (t) = quad (t>>2) x qlane (t&3). Lane holds channels
// {qlane*4 + 16j + u} of all 4 quad queries -> each candidate float4 read
// feeds 16 FMAs (4 queries x 4 channels): 4.0 FMA/float, and the quad's four
// float4 addresses hit 16 distinct banks (offsets 0/16/32/48B) -> conflict-
// free broadcast LDS (R10/R11 had 2-way conflicts at half*32 windows).
// 3-shfl reduce-scatter gives each lane its OWN query's full sum ->
// per-lane top-K (inserts for 4 queries run in parallel across lanes).
// ---------------------------------------------------------------------------
__global__ void __launch_bounds__(128) knn_part_kernel(
    const float* __restrict__ x)
{
    __shared__ float s_xm[TM][68];     // [m][c] candidate tile, padded
    __shared__ float s_xx[TM];
    __shared__ float s_td[KNN][QB];    // per-query top-20 distances
    __shared__ int   s_ti[KNN][QB];    // per-query top-20 indices

    const int t     = threadIdx.x;
    const int quad  = t >> 2;
    const int qlane = t & 3;
    const int bit0  = t & 1;
    const int bit1  = (t >> 1) & 1;
    const int p     = blockIdx.y;
    const int b     = blockIdx.z;
    const int qbase = blockIdx.x * QB + quad * 4;
    const int nown  = qbase + qlane;       // this lane's own query
    const int cbase = p * PCAND;
    const float* xb = x + (size_t)b * CIN * NPTS;

    // 16 channels (interleaved windows) of all 4 quad queries: xq[i*16 + j*4 + u]
    float xq[64];
#pragma unroll
    for (int i = 0; i < 4; i++)
#pragma unroll
        for (int j = 0; j < 4; j++)
#pragma unroll
            for (int u = 0; u < 4; u++)
                xq[i*16 + j*4 + u] =
                    xb[(size_t)(qlane*4 + j*16 + u) * NPTS + (qbase + i)];

    const float xxq = g_xx[(size_t)b * NPTS + nown];

    // init own top-k list (column t; local query index == t by construction)
    float* tdc = &s_td[0][t];
    int*   tic = &s_ti[0][t];
#pragma unroll
    for (int k = 0; k < KNN; k++) { tdc[k * QB] = 1e30f; tic[k * QB] = 0; }
    float kmax = 1e30f; int kpos = 0;

    // cooperative tile loader (R5 mapping, unchanged)
    const int lc = t >> 1;
    const int lm = (t & 1) * 32;
    const float* lptr = xb + (size_t)lc * NPTS + cbase + lm;
    const float* xxp  = g_xx + (size_t)b * NPTS + cbase;

    float4 ld[8]; float xld = 0.f;

    // prologue: tile 0
#pragma unroll
    for (int j = 0; j < 8; j++) ld[j] = *(const float4*)(lptr + 4 * j);
    if (t < TM) xld = xxp[t];
#pragma unroll
    for (int j = 0; j < 8; j++) {
        int m = lm + 4 * j;
        s_xm[m+0][lc] = ld[j].x; s_xm[m+1][lc] = ld[j].y;
        s_xm[m+2][lc] = ld[j].z; s_xm[m+3][lc] = ld[j].w;
    }
    if (t < TM) s_xx[t] = xld;
    __syncthreads();

    const int cw = qlane * 4;   // base offset of this lane's interleaved windows

#pragma unroll 1
    for (int tile = 0; tile < NT; tile++) {
        // prefetch next tile into registers
        if (tile + 1 < NT) {
            const float* pp = lptr + (tile + 1) * TM;
#pragma unroll
            for (int j = 0; j < 8; j++) ld[j] = *(const float4*)(pp + 4 * j);
            if (t < TM) xld = xxp[(tile + 1) * TM + t];
        }

        const int mbase = cbase + tile * TM;
#pragma unroll 1
        for (int mg = 0; mg < TM; mg += 4) {
            float acc[4][4];
#pragma unroll
            for (int i = 0; i < 4; i++)
#pragma unroll
                for (int m = 0; m < 4; m++) acc[i][m] = 0.f;

#pragma unroll
            for (int j = 0; j < 4; j++) {
                const int co = cw + j * 16;
                const float4 v0 = *(const float4*)(&s_xm[mg+0][co]);
                const float4 v1 = *(const float4*)(&s_xm[mg+1][co]);
                const float4 v2 = *(const float4*)(&s_xm[mg+2][co]);
                const float4 v3 = *(const float4*)(&s_xm[mg+3][co]);
#pragma unroll
                for (int i = 0; i < 4; i++) {
                    const float q0 = xq[i*16 + j*4 + 0];
                    const float q1 = xq[i*16 + j*4 + 1];
                    const float q2 = xq[i*16 + j*4 + 2];
                    const float q3 = xq[i*16 + j*4 + 3];
                    acc[i][0] = fmaf(q0, v0.x, acc[i][0]);
                    acc[i][0] = fmaf(q1, v0.y, acc[i][0]);
                    acc[i][0] = fmaf(q2, v0.z, acc[i][0]);
                    acc[i][0] = fmaf(q3, v0.w, acc[i][0]);
                    acc[i][1] = fmaf(q0, v1.x, acc[i][1]);
                    acc[i][1] = fmaf(q1, v1.y, acc[i][1]);
                    acc[i][1] = fmaf(q2, v1.z, acc[i][1]);
                    acc[i][1] = fmaf(q3, v1.w, acc[i][1]);
                    acc[i][2] = fmaf(q0, v2.x, acc[i][2]);
                    acc[i][2] = fmaf(q1, v2.y, acc[i][2]);
                    acc[i][2] = fmaf(q2, v2.z, acc[i][2]);
                    acc[i][2] = fmaf(q3, v2.w, acc[i][2]);
                    acc[i][3] = fmaf(q0, v3.x, acc[i][3]);
                    acc[i][3] = fmaf(q1, v3.y, acc[i][3]);
                    acc[i][3] = fmaf(q2, v3.z, acc[i][3]);
                    acc[i][3] = fmaf(q3, v3.w, acc[i][3]);
                }
            }

            // 3-shfl reduce-scatter per candidate: lane ends with OWN query's sum.
            float e[4];
#pragma unroll
            for (int m = 0; m < 4; m++) {
                const float p0 = acc[0][m], p1 = acc[1][m];
                const float p2 = acc[2][m], p3 = acc[3][m];
                // step 1 (xor 1): pair-total for queries {bit0, bit0+2}
                const float s1 = bit0 ? p0 : p1;          // partner needs P[bit0^1]
                const float s2 = bit0 ? p2 : p3;          // partner needs P[(bit0^1)+2]
                const float r1 = __shfl_xor_sync(0xffffffffu, s1, 1);
                const float r2 = __shfl_xor_sync(0xffffffffu, s2, 1);
                const float qlo = (bit0 ? p1 : p0) + r1;  // query bit0
                const float qhi = (bit0 ? p3 : p2) + r2;  // query bit0+2
                // step 2 (xor 2): quad-total for own query bit0+2*bit1
                const float s3 = bit1 ? qlo : qhi;
                const float r3 = __shfl_xor_sync(0xffffffffu, s3, 2);
                const float S  = (bit1 ? qhi : qlo) + r3;
                e[m] = fmaf(S, -2.f, xxq + s_xx[mg + m]);
            }

            const float emin = fminf(fminf(e[0], e[1]), fminf(e[2], e[3]));
            if (emin < kmax) {
                if (e[0] < kmax) insert20s(tdc, tic, kmax, kpos, e[0], mbase + mg + 0);
                if (e[1] < kmax) insert20s(tdc, tic, kmax, kpos, e[1], mbase + mg + 1);
                if (e[2] < kmax) insert20s(tdc, tic, kmax, kpos, e[2], mbase + mg + 2);
                if (e[3] < kmax) insert20s(tdc, tic, kmax, kpos, e[3], mbase + mg + 3);
            }
        }
        __syncthreads();
        if (tile + 1 < NT) {
#pragma unroll
            for (int j = 0; j < 8; j++) {
                int m = lm + 4 * j;
                s_xm[m+0][lc] = ld[j].x; s_xm[m+1][lc] = ld[j].y;
                s_xm[m+2][lc] = ld[j].z; s_xm[m+3][lc] = ld[j].w;
            }
            if (t < TM) s_xx[t] = xld;
        }
        __syncthreads();
    }

    // spill partition-local top-20 (local query == t; coalesced over n)
    {
        const int n = blockIdx.x * QB + t;
        float* tdo = g_ptd + (size_t)(b * PARTS + p) * KNN * NPTS + n;
        int*   tio = g_pti + (size_t)(b * PARTS + p) * KNN * NPTS + n;
#pragma unroll
        for (int k = 0; k < KNN; k++) {
            tdo[(size_t)k * NPTS] = s_td[k][t];
            tio[(size_t)k * NPTS] = s_ti[k][t];
        }
    }
}

// ---------------------------------------------------------------------------
// Kernel C: merge partition lists (ascending partition order preserves
// lowest-index tie-break; validated R8/R9/R11) + gather-max + BN/leaky epilogue.
// ---------------------------------------------------------------------------
__device__ __forceinline__ void insert20r(float (&td)[KNN], int (&ti)[KNN],
                                          float& kmax, int& kpos,
                                          float d, int m)
{
#pragma unroll
    for (int k = 0; k < KNN; k++) {
        if (k == kpos) { td[k] = d; ti[k] = m; }
    }
    float mx = -1e30f; int mp = 0;
#pragma unroll
    for (int k = 0; k < KNN; k++) {
        if (td[k] > mx) { mx = td[k]; mp = k; }
    }
    kmax = mx; kpos = mp;
}

__global__ void __launch_bounds__(128) merge_kernel(float* __restrict__ out)
{
    const int t = threadIdx.x;
    const int b = blockIdx.y;
    const int n = blockIdx.x * 128 + t;

    const float* tdp = g_ptd + (size_t)b * PARTS * KNN * NPTS + n;
    const int*   tip = g_pti + (size_t)b * PARTS * KNN * NPTS + n;

    float td[KNN]; int ti[KNN];
#pragma unroll
    for (int k = 0; k < KNN; k++) {
        td[k] = tdp[(size_t)k * NPTS];
        ti[k] = tip[(size_t)k * NPTS];
    }
    float kmax = -1e30f; int kpos = 0;
#pragma unroll
    for (int k = 0; k < KNN; k++) {
        if (td[k] > kmax) { kmax = td[k]; kpos = k; }
    }

#pragma unroll 1
    for (int p = 1; p < PARTS; p++) {
        const float* tdq = tdp + (size_t)p * KNN * NPTS;
        const int*   tiq = tip + (size_t)p * KNN * NPTS;
#pragma unroll
        for (int k = 0; k < KNN; k++) {
            float d = tdq[(size_t)k * NPTS];
            if (d < kmax) {
                int m = tiq[(size_t)k * NPTS];
                insert20r(td, ti, kmax, kpos, d, m);
            }
        }
    }

    // out[b][o][n] = leaky(zp[n][o] + max_k y2p[idx_k][o])
    const float* y2b = g_y2p + (size_t)b * NPTS * COUT;
    float4 acc[16];
#pragma unroll
    for (int j = 0; j < 16; j++) acc[j] = make_float4(-1e30f, -1e30f, -1e30f, -1e30f);

#pragma unroll
    for (int k = 0; k < KNN; k++) {
        const float4* row = (const float4*)(y2b + (size_t)ti[k] * COUT);
#pragma unroll
        for (int j = 0; j < 16; j++) {
            float4 v = row[j];
            acc[j].x = fmaxf(acc[j].x, v.x);
            acc[j].y = fmaxf(acc[j].y, v.y);
            acc[j].z = fmaxf(acc[j].z, v.z);
            acc[j].w = fmaxf(acc[j].w, v.w);
        }
    }

    const float4* zr = (const float4*)(g_zp + ((size_t)b * NPTS + n) * COUT);
    float* ob = out + (size_t)b * COUT * NPTS + n;
#pragma unroll
    for (int j = 0; j < 16; j++) {
        float4 z = zr[j];
        float r0 = z.x + acc[j].x; r0 = (r0 >= 0.f) ? r0 : 0.2f * r0;
        float r1 = z.y + acc[j].y; r1 = (r1 >= 0.f) ? r1 : 0.2f * r1;
        float r2 = z.z + acc[j].z; r2 = (r2 >= 0.f) ? r2 : 0.2f * r2;
        float r3 = z.w + acc[j].w; r3 = (r3 >= 0.f) ? r3 : 0.2f * r3;
        ob[(size_t)(4*j+0) * NPTS] = r0;
        ob[(size_t)(4*j+1) * NPTS] = r1;
        ob[(size_t)(4*j+2) * NPTS] = r2;
        ob[(size_t)(4*j+3) * NPTS] = r3;
    }
}

// ---------------------------------------------------------------------------
extern "C" void kernel_launch(void* const* d_in, const int* in_sizes, int n_in,
                              void* d_out, int out_size)
{
    const float* x     = (const float*)d_in[0];
    const float* W     = (const float*)d_in[1];
    const float* gamma = (const float*)d_in[2];
    const float* beta  = (const float*)d_in[3];
    const float* rmean = (const float*)d_in[4];
    const float* rvar  = (const float*)d_in[5];
    float* out = (float*)d_out;

    (void)in_sizes; (void)n_in; (void)out_size;

    prep_kernel<<<dim3(NPTS / 128, BATCH), 128>>>(x, W, gamma, beta, rmean, rvar);
    knn_part_kernel<<<dim3(NPTS / QB, PARTS, BATCH), 128>>>(x);
    merge_kernel<<<dim3(NPTS / 128, BATCH), 128>>>(out);
}

// round 13
// speedup vs baseline: 4.7644x; 1.1057x over previous
#include <cuda_runtime.h>
#include <cstddef>
#include <cstdint>

#define BATCH 8
#define CIN 64
#define NPTS 4096
#define COUT 64
#define KNN 20
#define TM 64
#define QB 128                 // queries per block (4 per lane-quad)
#define PARTS 2
#define PCAND (NPTS / PARTS)   // 2048 candidates per partition
#define NT (PCAND / TM)        // 32 tiles

// scratch (device globals: no allocations allowed)
__device__ float g_y2p[(size_t)BATCH * NPTS * COUT];  // a*(x . W2)
__device__ float g_zp [(size_t)BATCH * NPTS * COUT];  // a*(x . (W1-W2)) + beta - a*mean
__device__ float g_xx [(size_t)BATCH * NPTS];         // ||x_n||^2
__device__ float g_ptd[(size_t)BATCH * PARTS * KNN * NPTS];  // [b][p][k][n]
__device__ int   g_pti[(size_t)BATCH * PARTS * KNN * NPTS];

// ---------------------------------------------------------------------------
// Kernel A: per-point projections + BN folding + ||x||^2  (unchanged, ~48us)
// ---------------------------------------------------------------------------
__global__ void __launch_bounds__(128) prep_kernel(
    const float* __restrict__ x, const float* __restrict__ W,
    const float* __restrict__ gamma, const float* __restrict__ beta,
    const float* __restrict__ rmean, const float* __restrict__ rvar)
{
    __shared__ float sW[COUT * 2 * CIN];   // 64 x 128
    __shared__ float sA[COUT], sC0[COUT];

    const int t = threadIdx.x;
    const int b = blockIdx.y;
    const int n = blockIdx.x * 128 + t;

    for (int i = t; i < 2048; i += 128)
        ((float4*)sW)[i] = ((const float4*)W)[i];
    if (t < COUT) {
        float a = rsqrtf(rvar[t] + 1e-5f) * gamma[t];
        sA[t] = a;
        sC0[t] = fmaf(-a, rmean[t], beta[t]);
    }
    __syncthreads();

    const float* xb = x + (size_t)b * CIN * NPTS;
    float xq[CIN];
#pragma unroll
    for (int c = 0; c < CIN; c++) xq[c] = xb[(size_t)c * NPTS + n];

    float xx = 0.f;
#pragma unroll
    for (int c = 0; c < CIN; c++) xx = fmaf(xq[c], xq[c], xx);
    g_xx[(size_t)b * NPTS + n] = xx;

    float* y2r = g_y2p + ((size_t)b * NPTS + n) * COUT;
    float* zr  = g_zp  + ((size_t)b * NPTS + n) * COUT;

#pragma unroll 1
    for (int o = 0; o < COUT; o++) {
        const float* wr = sW + o * 128;
        float s2 = 0.f, sz = 0.f;
#pragma unroll
        for (int c = 0; c < 16; c++) {
            float4 w1 = *(const float4*)(wr + c * 4);
            float4 w2 = *(const float4*)(wr + 64 + c * 4);
            float q0 = xq[4*c+0], q1 = xq[4*c+1], q2 = xq[4*c+2], q3 = xq[4*c+3];
            s2 = fmaf(q0, w2.x, s2); sz = fmaf(q0, w1.x - w2.x, sz);
            s2 = fmaf(q1, w2.y, s2); sz = fmaf(q1, w1.y - w2.y, sz);
            s2 = fmaf(q2, w2.z, s2); sz = fmaf(q2, w1.z - w2.z, sz);
            s2 = fmaf(q3, w2.w, s2); sz = fmaf(q3, w1.w - w2.w, sz);
        }
        float a = sA[o];
        y2r[o] = a * s2;
        zr[o]  = fmaf(a, sz, sC0[o]);
    }
}

// ---------------------------------------------------------------------------
// smem top-20 insertion: replace current max, rescan. Column stride QB keeps
// lanes on distinct banks. Ascending-m scan with strict '<' reproduces
// lax.top_k lowest-index tiebreak.
// ---------------------------------------------------------------------------
__device__ __forceinline__ void insert20s(float* __restrict__ tdc,
                                          int* __restrict__ tic,
                                          float& kmax, int& kpos,
                                          float d, int m)
{
    tdc[kpos * QB] = d;
    tic[kpos * QB] = m;
    float mx = -1e30f; int mp = 0;
#pragma unroll
    for (int k = 0; k < KNN; k++) {
        float v = tdc[k * QB];
        if (v > mx) { mx = v; mp = k; }
    }
    kmax = mx; kpos = mp;
}

// ---------------------------------------------------------------------------
// Kernel B: knn, 4 queries per lane-quad, interleaved channel windows
// (R12 structure, proven). R13 change: the ld[8] register double-buffer is
// gone (-32 regs) -> target <=128 regs -> 4 blocks/SM -> the 512-block grid
// fits in ONE wave (592 slots), fixing R12's 58% slot utilization (3 blocks/
// SM = 444 slots < 512 -> 2 sequential rounds on 68 SMs). Tiles are loaded
// LDG->STS in two 4-float4 rounds; the ~250cyc L2-hit stall per tile is
// covered by the other 3 resident blocks.
// ---------------------------------------------------------------------------
__global__ void __launch_bounds__(128, 4) knn_part_kernel(
    const float* __restrict__ x)
{
    __shared__ float s_xm[TM][68];     // [m][c] candidate tile, padded
    __shared__ float s_xx[TM];
    __shared__ float s_td[KNN][QB];    // per-query top-20 distances
    __shared__ int   s_ti[KNN][QB];    // per-query top-20 indices

    const int t     = threadIdx.x;
    const int quad  = t >> 2;
    const int qlane = t & 3;
    const int bit0  = t & 1;
    const int bit1  = (t >> 1) & 1;
    const int p     = blockIdx.y;
    const int b     = blockIdx.z;
    const int qbase = blockIdx.x * QB + quad * 4;
    const int nown  = qbase + qlane;       // this lane's own query
    const int cbase = p * PCAND;
    const float* xb = x + (size_t)b * CIN * NPTS;

    // 16 channels (interleaved windows) of all 4 quad queries: xq[i*16 + j*4 + u]
    float xq[64];
#pragma unroll
    for (int i = 0; i < 4; i++)
#pragma unroll
        for (int j = 0; j < 4; j++)
#pragma unroll
            for (int u = 0; u < 4; u++)
                xq[i*16 + j*4 + u] =
                    xb[(size_t)(qlane*4 + j*16 + u) * NPTS + (qbase + i)];

    const float xxq = g_xx[(size_t)b * NPTS + nown];

    // init own top-k list (column t; local query index == t by construction)
    float* tdc = &s_td[0][t];
    int*   tic = &s_ti[0][t];
#pragma unroll
    for (int k = 0; k < KNN; k++) { tdc[k * QB] = 1e30f; tic[k * QB] = 0; }
    float kmax = 1e30f; int kpos = 0;

    // cooperative tile loader (R5 mapping): thread -> (channel, m-half)
    const int lc = t >> 1;
    const int lm = (t & 1) * 32;
    const float* lptr = xb + (size_t)lc * NPTS + cbase + lm;
    const float* xxp  = g_xx + (size_t)b * NPTS + cbase;

    const int cw = qlane * 4;   // base offset of this lane's interleaved windows

#pragma unroll 1
    for (int tile = 0; tile < NT; tile++) {
        // load tile straight into smem (two 4-float4 rounds, temps reused)
        {
            const float* pp = lptr + tile * TM;
            float4 l0 = *(const float4*)(pp + 0);
            float4 l1 = *(const float4*)(pp + 4);
            float4 l2 = *(const float4*)(pp + 8);
            float4 l3 = *(const float4*)(pp + 12);
            s_xm[lm+ 0][lc] = l0.x; s_xm[lm+ 1][lc] = l0.y;
            s_xm[lm+ 2][lc] = l0.z; s_xm[lm+ 3][lc] = l0.w;
            s_xm[lm+ 4][lc] = l1.x; s_xm[lm+ 5][lc] = l1.y;
            s_xm[lm+ 6][lc] = l1.z; s_xm[lm+ 7][lc] = l1.w;
            s_xm[lm+ 8][lc] = l2.x; s_xm[lm+ 9][lc] = l2.y;
            s_xm[lm+10][lc] = l2.z; s_xm[lm+11][lc] = l2.w;
            s_xm[lm+12][lc] = l3.x; s_xm[lm+13][lc] = l3.y;
            s_xm[lm+14][lc] = l3.z; s_xm[lm+15][lc] = l3.w;
            l0 = *(const float4*)(pp + 16);
            l1 = *(const float4*)(pp + 20);
            l2 = *(const float4*)(pp + 24);
            l3 = *(const float4*)(pp + 28);
            s_xm[lm+16][lc] = l0.x; s_xm[lm+17][lc] = l0.y;
            s_xm[lm+18][lc] = l0.z; s_xm[lm+19][lc] = l0.w;
            s_xm[lm+20][lc] = l1.x; s_xm[lm+21][lc] = l1.y;
            s_xm[lm+22][lc] = l1.z; s_xm[lm+23][lc] = l1.w;
            s_xm[lm+24][lc] = l2.x; s_xm[lm+25][lc] = l2.y;
            s_xm[lm+26][lc] = l2.z; s_xm[lm+27][lc] = l2.w;
            s_xm[lm+28][lc] = l3.x; s_xm[lm+29][lc] = l3.y;
            s_xm[lm+30][lc] = l3.z; s_xm[lm+31][lc] = l3.w;
            if (t < TM) s_xx[t] = xxp[tile * TM + t];
        }
        __syncthreads();

        const int mbase = cbase + tile * TM;
#pragma unroll 1
        for (int mg = 0; mg < TM; mg += 4) {
            float acc[4][4];
#pragma unroll
            for (int i = 0; i < 4; i++)
#pragma unroll
                for (int m = 0; m < 4; m++) acc[i][m] = 0.f;

#pragma unroll
            for (int j = 0; j < 4; j++) {
                const int co = cw + j * 16;
                const float4 v0 = *(const float4*)(&s_xm[mg+0][co]);
                const float4 v1 = *(const float4*)(&s_xm[mg+1][co]);
                const float4 v2 = *(const float4*)(&s_xm[mg+2][co]);
                const float4 v3 = *(const float4*)(&s_xm[mg+3][co]);
#pragma unroll
                for (int i = 0; i < 4; i++) {
                    const float q0 = xq[i*16 + j*4 + 0];
                    const float q1 = xq[i*16 + j*4 + 1];
                    const float q2 = xq[i*16 + j*4 + 2];
                    const float q3 = xq[i*16 + j*4 + 3];
                    acc[i][0] = fmaf(q0, v0.x, acc[i][0]);
                    acc[i][0] = fmaf(q1, v0.y, acc[i][0]);
                    acc[i][0] = fmaf(q2, v0.z, acc[i][0]);
                    acc[i][0] = fmaf(q3, v0.w, acc[i][0]);
                    acc[i][1] = fmaf(q0, v1.x, acc[i][1]);
                    acc[i][1] = fmaf(q1, v1.y, acc[i][1]);
                    acc[i][1] = fmaf(q2, v1.z, acc[i][1]);
                    acc[i][1] = fmaf(q3, v1.w, acc[i][1]);
                    acc[i][2] = fmaf(q0, v2.x, acc[i][2]);
                    acc[i][2] = fmaf(q1, v2.y, acc[i][2]);
                    acc[i][2] = fmaf(q2, v2.z, acc[i][2]);
                    acc[i][2] = fmaf(q3, v2.w, acc[i][2]);
                    acc[i][3] = fmaf(q0, v3.x, acc[i][3]);
                    acc[i][3] = fmaf(q1, v3.y, acc[i][3]);
                    acc[i][3] = fmaf(q2, v3.z, acc[i][3]);
                    acc[i][3] = fmaf(q3, v3.w, acc[i][3]);
                }
            }

            // 3-shfl reduce-scatter per candidate: lane ends with OWN query's sum.
            float e[4];
#pragma unroll
            for (int m = 0; m < 4; m++) {
                const float p0 = acc[0][m], p1 = acc[1][m];
                const float p2 = acc[2][m], p3 = acc[3][m];
                const float s1 = bit0 ? p0 : p1;
                const float s2 = bit0 ? p2 : p3;
                const float r1 = __shfl_xor_sync(0xffffffffu, s1, 1);
                const float r2 = __shfl_xor_sync(0xffffffffu, s2, 1);
                const float qlo = (bit0 ? p1 : p0) + r1;
                const float qhi = (bit0 ? p3 : p2) + r2;
                const float s3 = bit1 ? qlo : qhi;
                const float r3 = __shfl_xor_sync(0xffffffffu, s3, 2);
                const float S  = (bit1 ? qhi : qlo) + r3;
                e[m] = fmaf(S, -2.f, xxq + s_xx[mg + m]);
            }

            const float emin = fminf(fminf(e[0], e[1]), fminf(e[2], e[3]));
            if (emin < kmax) {
                if (e[0] < kmax) insert20s(tdc, tic, kmax, kpos, e[0], mbase + mg + 0);
                if (e[1] < kmax) insert20s(tdc, tic, kmax, kpos, e[1], mbase + mg + 1);
                if (e[2] < kmax) insert20s(tdc, tic, kmax, kpos, e[2], mbase + mg + 2);
                if (e[3] < kmax) insert20s(tdc, tic, kmax, kpos, e[3], mbase + mg + 3);
            }
        }
        __syncthreads();
    }

    // spill partition-local top-20 (local query == t; coalesced over n)
    {
        const int n = blockIdx.x * QB + t;
        float* tdo = g_ptd + (size_t)(b * PARTS + p) * KNN * NPTS + n;
        int*   tio = g_pti + (size_t)(b * PARTS + p) * KNN * NPTS + n;
#pragma unroll
        for (int k = 0; k < KNN; k++) {
            tdo[(size_t)k * NPTS] = s_td[k][t];
            tio[(size_t)k * NPTS] = s_ti[k][t];
        }
    }
}

// ---------------------------------------------------------------------------
// Kernel C: merge partition lists (ascending partition order preserves
// lowest-index tie-break; validated R8/R9/R11/R12) + gather-max + epilogue.
// ---------------------------------------------------------------------------
__device__ __forceinline__ void insert20r(float (&td)[KNN], int (&ti)[KNN],
                                          float& kmax, int& kpos,
                                          float d, int m)
{
#pragma unroll
    for (int k = 0; k < KNN; k++) {
        if (k == kpos) { td[k] = d; ti[k] = m; }
    }
    float mx = -1e30f; int mp = 0;
#pragma unroll
    for (int k = 0; k < KNN; k++) {
        if (td[k] > mx) { mx = td[k]; mp = k; }
    }
    kmax = mx; kpos = mp;
}

__global__ void __launch_bounds__(128) merge_kernel(float* __restrict__ out)
{
    const int t = threadIdx.x;
    const int b = blockIdx.y;
    const int n = blockIdx.x * 128 + t;

    const float* tdp = g_ptd + (size_t)b * PARTS * KNN * NPTS + n;
    const int*   tip = g_pti + (size_t)b * PARTS * KNN * NPTS + n;

    float td[KNN]; int ti[KNN];
#pragma unroll
    for (int k = 0; k < KNN; k++) {
        td[k] = tdp[(size_t)k * NPTS];
        ti[k] = tip[(size_t)k * NPTS];
    }
    float kmax = -1e30f; int kpos = 0;
#pragma unroll
    for (int k = 0; k < KNN; k++) {
        if (td[k] > kmax) { kmax = td[k]; kpos = k; }
    }

#pragma unroll 1
    for (int p = 1; p < PARTS; p++) {
        const float* tdq = tdp + (size_t)p * KNN * NPTS;
        const int*   tiq = tip + (size_t)p * KNN * NPTS;
#pragma unroll
        for (int k = 0; k < KNN; k++) {
            float d = tdq[(size_t)k * NPTS];
            if (d < kmax) {
                int m = tiq[(size_t)k * NPTS];
                insert20r(td, ti, kmax, kpos, d, m);
            }
        }
    }

    // out[b][o][n] = leaky(zp[n][o] + max_k y2p[idx_k][o])
    const float* y2b = g_y2p + (size_t)b * NPTS * COUT;
    float4 acc[16];
#pragma unroll
    for (int j = 0; j < 16; j++) acc[j] = make_float4(-1e30f, -1e30f, -1e30f, -1e30f);

#pragma unroll
    for (int k = 0; k < KNN; k++) {
        const float4* row = (const float4*)(y2b + (size_t)ti[k] * COUT);
#pragma unroll
        for (int j = 0; j < 16; j++) {
            float4 v = row[j];
            acc[j].x = fmaxf(acc[j].x, v.x);
            acc[j].y = fmaxf(acc[j].y, v.y);
            acc[j].z = fmaxf(acc[j].z, v.z);
            acc[j].w = fmaxf(acc[j].w, v.w);
        }
    }

    const float4* zr = (const float4*)(g_zp + ((size_t)b * NPTS + n) * COUT);
    float* ob = out + (size_t)b * COUT * NPTS + n;
#pragma unroll
    for (int j = 0; j < 16; j++) {
        float4 z = zr[j];
        float r0 = z.x + acc[j].x; r0 = (r0 >= 0.f) ? r0 : 0.2f * r0;
        float r1 = z.y + acc[j].y; r1 = (r1 >= 0.f) ? r1 : 0.2f * r1;
        float r2 = z.z + acc[j].z; r2 = (r2 >= 0.f) ? r2 : 0.2f * r2;
        float r3 = z.w + acc[j].w; r3 = (r3 >= 0.f) ? r3 : 0.2f * r3;
        ob[(size_t)(4*j+0) * NPTS] = r0;
        ob[(size_t)(4*j+1) * NPTS] = r1;
        ob[(size_t)(4*j+2) * NPTS] = r2;
        ob[(size_t)(4*j+3) * NPTS] = r3;
    }
}

// ---------------------------------------------------------------------------
extern "C" void kernel_launch(void* const* d_in, const int* in_sizes, int n_in,
                              void* d_out, int out_size)
{
    const float* x     = (const float*)d_in[0];
    const float* W     = (const float*)d_in[1];
    const float* gamma = (const float*)d_in[2];
    const float* beta  = (const float*)d_in[3];
    const float* rmean = (const float*)d_in[4];
    const float* rvar  = (const float*)d_in[5];
    float* out = (float*)d_out;

    (void)in_sizes; (void)n_in; (void)out_size;

    prep_kernel<<<dim3(NPTS / 128, BATCH), 128>>>(x, W, gamma, beta, rmean, rvar);
    knn_part_kernel<<<dim3(NPTS / QB, PARTS, BATCH), 128>>>(x);
    merge_kernel<<<dim3(NPTS / 128, BATCH), 128>>>(out);
}

// round 14
// speedup vs baseline: 4.8910x; 1.0266x over previous
#include <cuda_runtime.h>
#include <cstddef>
#include <cstdint>

#define BATCH 8
#define CIN 64
#define NPTS 4096
#define COUT 64
#define KNN 20
#define TM 64
#define QB 128                 // queries per block (4 per lane-quad)
#define PARTS 2
#define PCAND (NPTS / PARTS)   // 2048 candidates per partition
#define NT (PCAND / TM)        // 32 tiles

typedef unsigned long long ull;

// packed f32x2 helpers (sm_103a FFMA2 — only reachable via PTX)
#define FMA2(acc, a, b) \
    asm("fma.rn.f32x2 %0, %1, %2, %0;" : "+l"(acc) : "l"(a), "l"(b))
#define PACK2(out, lo, hi) \
    asm("mov.b64 %0, {%1, %2};" : "=l"(out) : "r"(__float_as_uint(lo)), "r"(__float_as_uint(hi)))

__device__ __forceinline__ float unpack_add(ull v) {
    unsigned lo, hi;
    asm("mov.b64 {%0, %1}, %2;" : "=r"(lo), "=r"(hi) : "l"(v));
    return __uint_as_float(lo) + __uint_as_float(hi);
}

// scratch (device globals: no allocations allowed)
__device__ float g_y2p[(size_t)BATCH * NPTS * COUT];  // a*(x . W2)
__device__ float g_zp [(size_t)BATCH * NPTS * COUT];  // a*(x . (W1-W2)) + beta - a*mean
__device__ float g_xx [(size_t)BATCH * NPTS];         // ||x_n||^2
__device__ float g_ptd[(size_t)BATCH * PARTS * KNN * NPTS];  // [b][p][k][n]
__device__ int   g_pti[(size_t)BATCH * PARTS * KNN * NPTS];

// ---------------------------------------------------------------------------
// Kernel A: per-point projections + BN folding + ||x||^2  (unchanged, ~48us)
// ---------------------------------------------------------------------------
__global__ void __launch_bounds__(128) prep_kernel(
    const float* __restrict__ x, const float* __restrict__ W,
    const float* __restrict__ gamma, const float* __restrict__ beta,
    const float* __restrict__ rmean, const float* __restrict__ rvar)
{
    __shared__ float sW[COUT * 2 * CIN];   // 64 x 128
    __shared__ float sA[COUT], sC0[COUT];

    const int t = threadIdx.x;
    const int b = blockIdx.y;
    const int n = blockIdx.x * 128 + t;

    for (int i = t; i < 2048; i += 128)
        ((float4*)sW)[i] = ((const float4*)W)[i];
    if (t < COUT) {
        float a = rsqrtf(rvar[t] + 1e-5f) * gamma[t];
        sA[t] = a;
        sC0[t] = fmaf(-a, rmean[t], beta[t]);
    }
    __syncthreads();

    const float* xb = x + (size_t)b * CIN * NPTS;
    float xq[CIN];
#pragma unroll
    for (int c = 0; c < CIN; c++) xq[c] = xb[(size_t)c * NPTS + n];

    float xx = 0.f;
#pragma unroll
    for (int c = 0; c < CIN; c++) xx = fmaf(xq[c], xq[c], xx);
    g_xx[(size_t)b * NPTS + n] = xx;

    float* y2r = g_y2p + ((size_t)b * NPTS + n) * COUT;
    float* zr  = g_zp  + ((size_t)b * NPTS + n) * COUT;

#pragma unroll 1
    for (int o = 0; o < COUT; o++) {
        const float* wr = sW + o * 128;
        float s2 = 0.f, sz = 0.f;
#pragma unroll
        for (int c = 0; c < 16; c++) {
            float4 w1 = *(const float4*)(wr + c * 4);
            float4 w2 = *(const float4*)(wr + 64 + c * 4);
            float q0 = xq[4*c+0], q1 = xq[4*c+1], q2 = xq[4*c+2], q3 = xq[4*c+3];
            s2 = fmaf(q0, w2.x, s2); sz = fmaf(q0, w1.x - w2.x, sz);
            s2 = fmaf(q1, w2.y, s2); sz = fmaf(q1, w1.y - w2.y, sz);
            s2 = fmaf(q2, w2.z, s2); sz = fmaf(q2, w1.z - w2.z, sz);
            s2 = fmaf(q3, w2.w, s2); sz = fmaf(q3, w1.w - w2.w, sz);
        }
        float a = sA[o];
        y2r[o] = a * s2;
        zr[o]  = fmaf(a, sz, sC0[o]);
    }
}

// ---------------------------------------------------------------------------
// smem top-20 insertion: replace current max, rescan. Column stride QB keeps
// lanes on distinct banks. Ascending-m scan with strict '<' reproduces
// lax.top_k lowest-index tiebreak.
// ---------------------------------------------------------------------------
__device__ __forceinline__ void insert20s(float* __restrict__ tdc,
                                          int* __restrict__ tic,
                                          float& kmax, int& kpos,
                                          float d, int m)
{
    tdc[kpos * QB] = d;
    tic[kpos * QB] = m;
    float mx = -1e30f; int mp = 0;
#pragma unroll
    for (int k = 0; k < KNN; k++) {
        float v = tdc[k * QB];
        if (v > mx) { mx = v; mp = k; }
    }
    kmax = mx; kpos = mp;
}

// ---------------------------------------------------------------------------
// Kernel B: knn, 4 queries per lane-quad (R12/R13 structure, proven).
// R14 change: inner product uses packed fma.rn.f32x2 (FFMA2) — even/odd
// channel chains in one 64-bit accumulator -> scalar-FMA instruction count
// halves (131072 -> 65536/thread), halving the FMA-issue floor (~580us ->
// ~290us/SMSP). Candidate group is 2 (acc[4][2] packed = 16 regs, same
// footprint as R13's scalar acc[4][4]) to preserve 4 blocks/SM / one wave.
// ---------------------------------------------------------------------------
__global__ void __launch_bounds__(128, 4) knn_part_kernel(
    const float* __restrict__ x)
{
    __shared__ float s_xm[TM][68];     // [m][c] candidate tile, padded
    __shared__ float s_xx[TM];
    __shared__ float s_td[KNN][QB];    // per-query top-20 distances
    __shared__ int   s_ti[KNN][QB];    // per-query top-20 indices

    const int t     = threadIdx.x;
    const int quad  = t >> 2;
    const int qlane = t & 3;
    const int bit0  = t & 1;
    const int bit1  = (t >> 1) & 1;
    const int p     = blockIdx.y;
    const int b     = blockIdx.z;
    const int qbase = blockIdx.x * QB + quad * 4;
    const int nown  = qbase + qlane;       // this lane's own query
    const int cbase = p * PCAND;
    const float* xb = x + (size_t)b * CIN * NPTS;

    // 16 channels (interleaved windows) of 4 quad queries, packed in pairs:
    // xqp[i*8 + j*2 + h] = (ch qlane*4+j*16+2h, ch qlane*4+j*16+2h+1) of query qbase+i
    ull xqp[32];
#pragma unroll
    for (int i = 0; i < 4; i++)
#pragma unroll
        for (int j = 0; j < 4; j++)
#pragma unroll
            for (int h = 0; h < 2; h++) {
                const float lo = xb[(size_t)(qlane*4 + j*16 + 2*h + 0) * NPTS + (qbase + i)];
                const float hi = xb[(size_t)(qlane*4 + j*16 + 2*h + 1) * NPTS + (qbase + i)];
                PACK2(xqp[i*8 + j*2 + h], lo, hi);
            }

    const float xxq = g_xx[(size_t)b * NPTS + nown];

    // init own top-k list (column t; local query index == t by construction)
    float* tdc = &s_td[0][t];
    int*   tic = &s_ti[0][t];
#pragma unroll
    for (int k = 0; k < KNN; k++) { tdc[k * QB] = 1e30f; tic[k * QB] = 0; }
    float kmax = 1e30f; int kpos = 0;

    // cooperative tile loader (R5 mapping): thread -> (channel, m-half)
    const int lc = t >> 1;
    const int lm = (t & 1) * 32;
    const float* lptr = xb + (size_t)lc * NPTS + cbase + lm;
    const float* xxp  = g_xx + (size_t)b * NPTS + cbase;

    const int cw = qlane * 4;   // base offset of this lane's interleaved windows

#pragma unroll 1
    for (int tile = 0; tile < NT; tile++) {
        // load tile straight into smem (two 4-float4 rounds, temps reused)
        {
            const float* pp = lptr + tile * TM;
            float4 l0 = *(const float4*)(pp + 0);
            float4 l1 = *(const float4*)(pp + 4);
            float4 l2 = *(const float4*)(pp + 8);
            float4 l3 = *(const float4*)(pp + 12);
            s_xm[lm+ 0][lc] = l0.x; s_xm[lm+ 1][lc] = l0.y;
            s_xm[lm+ 2][lc] = l0.z; s_xm[lm+ 3][lc] = l0.w;
            s_xm[lm+ 4][lc] = l1.x; s_xm[lm+ 5][lc] = l1.y;
            s_xm[lm+ 6][lc] = l1.z; s_xm[lm+ 7][lc] = l1.w;
            s_xm[lm+ 8][lc] = l2.x; s_xm[lm+ 9][lc] = l2.y;
            s_xm[lm+10][lc] = l2.z; s_xm[lm+11][lc] = l2.w;
            s_xm[lm+12][lc] = l3.x; s_xm[lm+13][lc] = l3.y;
            s_xm[lm+14][lc] = l3.z; s_xm[lm+15][lc] = l3.w;
            l0 = *(const float4*)(pp + 16);
            l1 = *(const float4*)(pp + 20);
            l2 = *(const float4*)(pp + 24);
            l3 = *(const float4*)(pp + 28);
            s_xm[lm+16][lc] = l0.x; s_xm[lm+17][lc] = l0.y;
            s_xm[lm+18][lc] = l0.z; s_xm[lm+19][lc] = l0.w;
            s_xm[lm+20][lc] = l1.x; s_xm[lm+21][lc] = l1.y;
            s_xm[lm+22][lc] = l1.z; s_xm[lm+23][lc] = l1.w;
            s_xm[lm+24][lc] = l2.x; s_xm[lm+25][lc] = l2.y;
            s_xm[lm+26][lc] = l2.z; s_xm[lm+27][lc] = l2.w;
            s_xm[lm+28][lc] = l3.x; s_xm[lm+29][lc] = l3.y;
            s_xm[lm+30][lc] = l3.z; s_xm[lm+31][lc] = l3.w;
            if (t < TM) s_xx[t] = xxp[tile * TM + t];
        }
        __syncthreads();

        const int mbase = cbase + tile * TM;
#pragma unroll 1
        for (int mg = 0; mg < TM; mg += 2) {
            // packed accumulators: acc[i][m] holds (even-ch sum, odd-ch sum)
            ull acc[4][2];
#pragma unroll
            for (int i = 0; i < 4; i++) { acc[i][0] = 0ull; acc[i][1] = 0ull; }

#pragma unroll
            for (int j = 0; j < 4; j++) {
                const int co = cw + j * 16;
                const ulonglong2 v0 = *(const ulonglong2*)(&s_xm[mg+0][co]);
                const ulonglong2 v1 = *(const ulonglong2*)(&s_xm[mg+1][co]);
#pragma unroll
                for (int i = 0; i < 4; i++) {
                    const ull qlo = xqp[i*8 + j*2 + 0];
                    const ull qhi = xqp[i*8 + j*2 + 1];
                    FMA2(acc[i][0], qlo, v0.x);
                    FMA2(acc[i][0], qhi, v0.y);
                    FMA2(acc[i][1], qlo, v1.x);
                    FMA2(acc[i][1], qhi, v1.y);
                }
            }

            // per-candidate: unpack-add halves, 3-shfl reduce-scatter
            float e[2];
#pragma unroll
            for (int m = 0; m < 2; m++) {
                const float p0 = unpack_add(acc[0][m]);
                const float p1 = unpack_add(acc[1][m]);
                const float p2 = unpack_add(acc[2][m]);
                const float p3 = unpack_add(acc[3][m]);
                const float s1 = bit0 ? p0 : p1;
                const float s2 = bit0 ? p2 : p3;
                const float r1 = __shfl_xor_sync(0xffffffffu, s1, 1);
                const float r2 = __shfl_xor_sync(0xffffffffu, s2, 1);
                const float qlo = (bit0 ? p1 : p0) + r1;
                const float qhi = (bit0 ? p3 : p2) + r2;
                const float s3 = bit1 ? qlo : qhi;
                const float r3 = __shfl_xor_sync(0xffffffffu, s3, 2);
                const float S  = (bit1 ? qhi : qlo) + r3;
                e[m] = fmaf(S, -2.f, xxq + s_xx[mg + m]);
            }

            const float emin = fminf(e[0], e[1]);
            if (emin < kmax) {
                if (e[0] < kmax) insert20s(tdc, tic, kmax, kpos, e[0], mbase + mg + 0);
                if (e[1] < kmax) insert20s(tdc, tic, kmax, kpos, e[1], mbase + mg + 1);
            }
        }
        __syncthreads();
    }

    // spill partition-local top-20 (local query == t; coalesced over n)
    {
        const int n = blockIdx.x * QB + t;
        float* tdo = g_ptd + (size_t)(b * PARTS + p) * KNN * NPTS + n;
        int*   tio = g_pti + (size_t)(b * PARTS + p) * KNN * NPTS + n;
#pragma unroll
        for (int k = 0; k < KNN; k++) {
            tdo[(size_t)k * NPTS] = s_td[k][t];
            tio[(size_t)k * NPTS] = s_ti[k][t];
        }
    }
}

// ---------------------------------------------------------------------------
// Kernel C: merge partition lists (ascending partition order preserves
// lowest-index tie-break; validated R8-R13) + gather-max + epilogue.
// ---------------------------------------------------------------------------
__device__ __forceinline__ void insert20r(float (&td)[KNN], int (&ti)[KNN],
                                          float& kmax, int& kpos,
                                          float d, int m)
{
#pragma unroll
    for (int k = 0; k < KNN; k++) {
        if (k == kpos) { td[k] = d; ti[k] = m; }
    }
    float mx = -1e30f; int mp = 0;
#pragma unroll
    for (int k = 0; k < KNN; k++) {
        if (td[k] > mx) { mx = td[k]; mp = k; }
    }
    kmax = mx; kpos = mp;
}

__global__ void __launch_bounds__(128) merge_kernel(float* __restrict__ out)
{
    const int t = threadIdx.x;
    const int b = blockIdx.y;
    const int n = blockIdx.x * 128 + t;

    const float* tdp = g_ptd + (size_t)b * PARTS * KNN * NPTS + n;
    const int*   tip = g_pti + (size_t)b * PARTS * KNN * NPTS + n;

    float td[KNN]; int ti[KNN];
#pragma unroll
    for (int k = 0; k < KNN; k++) {
        td[k] = tdp[(size_t)k * NPTS];
        ti[k] = tip[(size_t)k * NPTS];
    }
    float kmax = -1e30f; int kpos = 0;
#pragma unroll
    for (int k = 0; k < KNN; k++) {
        if (td[k] > kmax) { kmax = td[k]; kpos = k; }
    }

#pragma unroll 1
    for (int p = 1; p < PARTS; p++) {
        const float* tdq = tdp + (size_t)p * KNN * NPTS;
        const int*   tiq = tip + (size_t)p * KNN * NPTS;
#pragma unroll
        for (int k = 0; k < KNN; k++) {
            float d = tdq[(size_t)k * NPTS];
            if (d < kmax) {
                int m = tiq[(size_t)k * NPTS];
                insert20r(td, ti, kmax, kpos, d, m);
            }
        }
    }

    // out[b][o][n] = leaky(zp[n][o] + max_k y2p[idx_k][o])
    const float* y2b = g_y2p + (size_t)b * NPTS * COUT;
    float4 acc[16];
#pragma unroll
    for (int j = 0; j < 16; j++) acc[j] = make_float4(-1e30f, -1e30f, -1e30f, -1e30f);

#pragma unroll
    for (int k = 0; k < KNN; k++) {
        const float4* row = (const float4*)(y2b + (size_t)ti[k] * COUT);
#pragma unroll
        for (int j = 0; j < 16; j++) {
            float4 v = row[j];
            acc[j].x = fmaxf(acc[j].x, v.x);
            acc[j].y = fmaxf(acc[j].y, v.y);
            acc[j].z = fmaxf(acc[j].z, v.z);
            acc[j].w = fmaxf(acc[j].w, v.w);
        }
    }

    const float4* zr = (const float4*)(g_zp + ((size_t)b * NPTS + n) * COUT);
    float* ob = out + (size_t)b * COUT * NPTS + n;
#pragma unroll
    for (int j = 0; j < 16; j++) {
        float4 z = zr[j];
        float r0 = z.x + acc[j].x; r0 = (r0 >= 0.f) ? r0 : 0.2f * r0;
        float r1 = z.y + acc[j].y; r1 = (r1 >= 0.f) ? r1 : 0.2f * r1;
        float r2 = z.z + acc[j].z; r2 = (r2 >= 0.f) ? r2 : 0.2f * r2;
        float r3 = z.w + acc[j].w; r3 = (r3 >= 0.f) ? r3 : 0.2f * r3;
        ob[(size_t)(4*j+0) * NPTS] = r0;
        ob[(size_t)(4*j+1) * NPTS] = r1;
        ob[(size_t)(4*j+2) * NPTS] = r2;
        ob[(size_t)(4*j+3) * NPTS] = r3;
    }
}

// ---------------------------------------------------------------------------
extern "C" void kernel_launch(void* const* d_in, const int* in_sizes, int n_in,
                              void* d_out, int out_size)
{
    const float* x     = (const float*)d_in[0];
    const float* W     = (const float*)d_in[1];
    const float* gamma = (const float*)d_in[2];
    const float* beta  = (const float*)d_in[3];
    const float* rmean = (const float*)d_in[4];
    const float* rvar  = (const float*)d_in[5];
    float* out = (float*)d_out;

    (void)in_sizes; (void)n_in; (void)out_size;

    prep_kernel<<<dim3(NPTS / 128, BATCH), 128>>>(x, W, gamma, beta, rmean, rvar);
    knn_part_kernel<<<dim3(NPTS / QB, PARTS, BATCH), 128>>>(x);
    merge_kernel<<<dim3(NPTS / 128, BATCH), 128>>>(out);
}